// round 9
// baseline (speedup 1.0000x reference)
#include <cuda_runtime.h>
#include <cuda_bf16.h>
#include <math_constants.h>

#define NA    4096
#define NB    4096
#define DIMK  128
#define NN    4097
#define SUPER 4096
#define ULLMAX 0xFFFFFFFFFFFFFFFFULL
#define NBLK  296          // persistent grid: 2 blocks/SM resident

typedef unsigned long long ull;

// ---------------- scratch ----------------
__device__ __align__(16) float    g_sqA[NA];
__device__ __align__(16) float    g_sqB[NB];
__device__ __align__(16) float    g_keyB[NB];      // exact sqrt(d^2(b, a*))
__device__ __align__(16) unsigned g_key2min[NB];   // exact fp32 bits of d^2(b, a*)
__device__ __align__(16) unsigned g_amin[NB];      // packed (approx d2 | a idx)
__device__ __align__(16) unsigned g_row1[NB];      // round-1 per-row min packed key
__device__ __align__(16) unsigned g_Abf[NA * 64];  // bf16x2 packed A points
__device__ __align__(16) unsigned g_Bbf[NB * 64];  // bf16x2 packed B points
__device__ __align__(16) unsigned g_BMIN[NB * 64]; // per-row per-64col block min (1MB)
__device__ __align__(16) unsigned g_KEY[(size_t)NB * NB];  // 64MB packed (d2w20|col12)
__device__ int  g_comp[NN];
__device__ ull  g_best[NN];
__device__ float g_total;
__device__ int   g_done;
__device__ unsigned          g_barcnt;
__device__ volatile unsigned g_barphase;

// ---------------- prep: squared norms + bf16x2 pack, one pass ----------------
__global__ __launch_bounds__(256) void prep_kernel(const float* __restrict__ batch,
                                                   const float* __restrict__ output) {
    int row  = blockIdx.x * 8 + (threadIdx.x >> 5);
    int lane = threadIdx.x & 31;
    bool isA = row < NA;
    const float* src = isA ? (batch + (size_t)row * DIMK)
                           : (output + (size_t)(row - NA) * DIMK);
    float4 v = ((const float4*)src)[lane];
    float s = v.x * v.x + v.y * v.y + v.z * v.z + v.w * v.w;

    __nv_bfloat162 b0 = __float22bfloat162_rn(make_float2(v.x, v.y));
    __nv_bfloat162 b1 = __float22bfloat162_rn(make_float2(v.z, v.w));
    uint2 w;
    w.x = *reinterpret_cast<unsigned*>(&b0);
    w.y = *reinterpret_cast<unsigned*>(&b1);
    unsigned* dst = isA ? (g_Abf + (size_t)row * 64) : (g_Bbf + (size_t)(row - NA) * 64);
    *(uint2*)(dst + lane * 2) = w;

    #pragma unroll
    for (int o = 16; o; o >>= 1) s += __shfl_down_sync(0xffffffffu, s, o);
    if (lane == 0) {
        if (isA) g_sqA[row] = s;
        else     g_sqB[row - NA] = s;
    }
}

// ---------------- init ----------------
__global__ __launch_bounds__(1024) void init_kernel() {
    int i = blockIdx.x * blockDim.x + threadIdx.x;
    int stride = gridDim.x * blockDim.x;
    for (int x = i; x < NN; x += stride) { g_comp[x] = x; g_best[x] = ULLMAX; }
    for (int x = i; x < NB; x += stride) { g_row1[x] = 0xFFFFFFFFu; g_amin[x] = 0xFFFFFFFFu; }
    if (i == 0) { g_total = 0.f; g_done = 0; g_barcnt = 0u; }
}

// ---------------- MMA + cp.async helpers ----------------
__device__ __forceinline__ void ldmx4(unsigned addr, unsigned& r0, unsigned& r1,
                                      unsigned& r2, unsigned& r3) {
    asm volatile("ldmatrix.sync.aligned.m8n8.x4.shared.b16 {%0,%1,%2,%3}, [%4];"
                 : "=r"(r0), "=r"(r1), "=r"(r2), "=r"(r3) : "r"(addr));
}
__device__ __forceinline__ void ldmx2(unsigned addr, unsigned& r0, unsigned& r1) {
    asm volatile("ldmatrix.sync.aligned.m8n8.x2.shared.b16 {%0,%1}, [%2];"
                 : "=r"(r0), "=r"(r1) : "r"(addr));
}
__device__ __forceinline__ void mma_bf16(float* c, unsigned a0, unsigned a1,
                                         unsigned a2, unsigned a3,
                                         unsigned b0, unsigned b1) {
    asm volatile("mma.sync.aligned.m16n8k16.row.col.f32.bf16.bf16.f32 "
                 "{%0,%1,%2,%3},{%4,%5,%6,%7},{%8,%9},{%0,%1,%2,%3};"
                 : "+f"(c[0]), "+f"(c[1]), "+f"(c[2]), "+f"(c[3])
                 : "r"(a0), "r"(a1), "r"(a2), "r"(a3), "r"(b0), "r"(b1));
}
__device__ __forceinline__ void cpa16(unsigned dst, const void* src) {
    asm volatile("cp.async.cg.shared.global [%0], [%1], 16;" :: "r"(dst), "l"(src));
}
__device__ __forceinline__ void cpa_commit() { asm volatile("cp.async.commit_group;"); }
template<int N> __device__ __forceinline__ void cpa_wait() {
    asm volatile("cp.async.wait_group %0;" :: "n"(N));
}

// chunk layout: 128 rows x 32 bf16 (4 x 16B groups); phys slot = r*4 + (g ^ (r&3))
__device__ __forceinline__ void load_chunk_async(unsigned sbase,
                                                 const unsigned* __restrict__ gsrc, int kc) {
    int tid = threadIdx.x;
    #pragma unroll
    for (int it = 0; it < 2; it++) {
        int f = tid + it * 256;
        int r = f >> 2, g = f & 3;
        cpa16(sbase + (unsigned)((r * 4 + (g ^ (r & 3))) << 4),
              gsrc + (size_t)r * 64 + kc * 16 + g * 4);
    }
}
__device__ __forceinline__ unsigned chunk_addr(unsigned base, int row, int g) {
    return base + (unsigned)((row * 4 + (g ^ (row & 3))) << 4);
}
__device__ __forceinline__ void afrag(unsigned base, int mt, int s, int lane,
                                      unsigned& a0, unsigned& a1, unsigned& a2, unsigned& a3) {
    int row = mt + (lane & 7) + ((lane >> 3) & 1) * 8;
    int g   = s * 2 + (lane >> 4);
    ldmx4(chunk_addr(base, row, g), a0, a1, a2, a3);
}
__device__ __forceinline__ void bfrag(unsigned base, int nt, int s, int lane,
                                      unsigned& b0, unsigned& b1) {
    int l15 = lane & 15;
    int row = nt + (l15 & 7);
    int g   = s * 2 + ((l15 >> 3) & 1);
    ldmx2(chunk_addr(base, row, g), b0, b1);
}

// double-buffered 128x128x128 bf16 MMA mainloop -> acc
__device__ __forceinline__ void mma_mainloop(unsigned basePu, unsigned baseQu,
                                             const unsigned* gP, const unsigned* gQ,
                                             float acc[2][8][4], int wm, int wn, int lane) {
    load_chunk_async(basePu, gP, 0);
    load_chunk_async(baseQu, gQ, 0);
    cpa_commit();
    #pragma unroll
    for (int kc = 0; kc < 4; kc++) {
        if (kc < 3) {
            unsigned off = (kc & 1) ? 0u : 8192u;
            load_chunk_async(basePu + off, gP, kc + 1);
            load_chunk_async(baseQu + off, gQ, kc + 1);
            cpa_commit();
            cpa_wait<1>();
        } else {
            cpa_wait<0>();
        }
        __syncthreads();
        unsigned off = (kc & 1) ? 8192u : 0u;
        #pragma unroll
        for (int s = 0; s < 2; s++) {
            unsigned a00, a01, a02, a03, a10, a11, a12, a13;
            afrag(basePu + off, wm,      s, lane, a00, a01, a02, a03);
            afrag(basePu + off, wm + 16, s, lane, a10, a11, a12, a13);
            #pragma unroll
            for (int j = 0; j < 8; j++) {
                unsigned b0, b1;
                bfrag(baseQu + off, wn + j * 8, s, lane, b0, b1);
                mma_bf16(acc[0][j], a00, a01, a02, a03, b0, b1);
                mma_bf16(acc[1][j], a10, a11, a12, a13, b0, b1);
            }
        }
        __syncthreads();
    }
}

// ---------------- K2: approx argmin_a d^2(b,a) ----------------
__global__ __launch_bounds__(256) void key_init_kernel()
{
    __shared__ __align__(16) uint4 sP[2][512];
    __shared__ __align__(16) uint4 sQ[2][512];
    __shared__ float sSqJ[128];

    const int tid = threadIdx.x, warp = tid >> 5, lane = tid & 31;
    const int m0 = blockIdx.y * 128;       // B rows
    const int n0 = blockIdx.x * 128;       // A cols
    const int wm = (warp & 3) * 32;
    const int wn = (warp >> 2) * 64;

    if (tid < 128) sSqJ[tid] = g_sqA[n0 + tid];

    unsigned basePu = (unsigned)__cvta_generic_to_shared(sP);
    unsigned baseQu = (unsigned)__cvta_generic_to_shared(sQ);

    float acc[2][8][4];
    #pragma unroll
    for (int mi = 0; mi < 2; mi++)
        #pragma unroll
        for (int j = 0; j < 8; j++)
            #pragma unroll
            for (int e = 0; e < 4; e++) acc[mi][j][e] = 0.f;

    mma_mainloop(basePu, baseQu, g_Bbf + (size_t)m0 * 64, g_Abf + (size_t)n0 * 64,
                 acc, wm, wn, lane);

    const int mlo = lane >> 2, ne = (lane & 3) * 2;
    float sqi[4];
    #pragma unroll
    for (int mi = 0; mi < 2; mi++) {
        sqi[mi * 2 + 0] = g_sqB[m0 + wm + mi * 16 + mlo];
        sqi[mi * 2 + 1] = g_sqB[m0 + wm + mi * 16 + 8 + mlo];
    }
    unsigned rmin[4] = {0xFFFFFFFFu, 0xFFFFFFFFu, 0xFFFFFFFFu, 0xFFFFFFFFu};
    #pragma unroll
    for (int mi = 0; mi < 2; mi++) {
        #pragma unroll
        for (int j = 0; j < 8; j++) {
            int nl = wn + j * 8 + ne;
            float sq0 = sSqJ[nl], sq1 = sSqJ[nl + 1];
            unsigned aj0 = (unsigned)(n0 + nl), aj1 = aj0 + 1;
            float d2;
            d2 = fmaxf(sqi[mi*2] + sq0 - 2.f * acc[mi][j][0], 0.f);
            rmin[mi*2]   = min(rmin[mi*2],   (__float_as_uint(d2) & 0xFFFFF000u) | aj0);
            d2 = fmaxf(sqi[mi*2] + sq1 - 2.f * acc[mi][j][1], 0.f);
            rmin[mi*2]   = min(rmin[mi*2],   (__float_as_uint(d2) & 0xFFFFF000u) | aj1);
            d2 = fmaxf(sqi[mi*2+1] + sq0 - 2.f * acc[mi][j][2], 0.f);
            rmin[mi*2+1] = min(rmin[mi*2+1], (__float_as_uint(d2) & 0xFFFFF000u) | aj0);
            d2 = fmaxf(sqi[mi*2+1] + sq1 - 2.f * acc[mi][j][3], 0.f);
            rmin[mi*2+1] = min(rmin[mi*2+1], (__float_as_uint(d2) & 0xFFFFF000u) | aj1);
        }
    }
    #pragma unroll
    for (int r = 0; r < 4; r++) {
        unsigned m = rmin[r];
        m = min(m, __shfl_xor_sync(0xffffffffu, m, 1));
        m = min(m, __shfl_xor_sync(0xffffffffu, m, 2));
        if ((lane & 3) == 0) {
            int row = m0 + wm + (r >> 1) * 16 + ((r & 1) ? 8 : 0) + mlo;
            atomicMin(&g_amin[row], m);
        }
    }
}

// ---------------- K3: packed d^2 key matrix + per-64col block mins ----------------
__global__ __launch_bounds__(256) void dbb_kernel()
{
    __shared__ __align__(16) uint4 sP[2][512];
    __shared__ __align__(16) uint4 sQ[2][512];
    __shared__ float sSqJ[128];

    const int tid = threadIdx.x, warp = tid >> 5, lane = tid & 31;
    const int m0 = blockIdx.y * 128;
    const int n0 = blockIdx.x * 128;
    const int wm = (warp & 3) * 32;
    const int wn = (warp >> 2) * 64;

    if (tid < 128) sSqJ[tid] = g_sqB[n0 + tid];

    unsigned basePu = (unsigned)__cvta_generic_to_shared(sP);
    unsigned baseQu = (unsigned)__cvta_generic_to_shared(sQ);

    float acc[2][8][4];
    #pragma unroll
    for (int mi = 0; mi < 2; mi++)
        #pragma unroll
        for (int j = 0; j < 8; j++)
            #pragma unroll
            for (int e = 0; e < 4; e++) acc[mi][j][e] = 0.f;

    mma_mainloop(basePu, baseQu, g_Bbf + (size_t)m0 * 64, g_Bbf + (size_t)n0 * 64,
                 acc, wm, wn, lane);

    const int mlo = lane >> 2, ne = (lane & 3) * 2;
    float sqi[4];
    int rowg[4];
    #pragma unroll
    for (int mi = 0; mi < 2; mi++) {
        rowg[mi*2]   = m0 + wm + mi * 16 + mlo;
        rowg[mi*2+1] = m0 + wm + mi * 16 + 8 + mlo;
        sqi[mi*2]    = g_sqB[rowg[mi*2]];
        sqi[mi*2+1]  = g_sqB[rowg[mi*2+1]];
    }
    unsigned rmin[4] = {0xFFFFFFFFu, 0xFFFFFFFFu, 0xFFFFFFFFu, 0xFFFFFFFFu};
    #pragma unroll
    for (int mi = 0; mi < 2; mi++) {
        #pragma unroll
        for (int j = 0; j < 8; j++) {
            int nl = wn + j * 8 + ne;
            int bj0 = n0 + nl, bj1 = bj0 + 1;
            float sq0 = sSqJ[nl], sq1 = sSqJ[nl + 1];
            #pragma unroll
            for (int h = 0; h < 2; h++) {
                int bi = rowg[mi*2 + h];
                float d20 = fmaxf(sqi[mi*2+h] + sq0 - 2.f * acc[mi][j][h*2+0], 0.f);
                float d21 = fmaxf(sqi[mi*2+h] + sq1 - 2.f * acc[mi][j][h*2+1], 0.f);
                unsigned pk0 = (__float_as_uint(d20) & 0xFFFFF000u) | (unsigned)bj0;
                unsigned pk1 = (__float_as_uint(d21) & 0xFFFFF000u) | (unsigned)bj1;
                if (bj0 != bi) rmin[mi*2+h] = min(rmin[mi*2+h], pk0);
                if (bj1 != bi) rmin[mi*2+h] = min(rmin[mi*2+h], pk1);
                *(uint2*)&g_KEY[(size_t)bi * NB + bj0] = make_uint2(pk0, pk1);
            }
        }
    }
    const int cblk = blockIdx.x * 2 + (warp >> 2);   // 64-col block index
    #pragma unroll
    for (int r = 0; r < 4; r++) {
        unsigned m = rmin[r];
        m = min(m, __shfl_xor_sync(0xffffffffu, m, 1));
        m = min(m, __shfl_xor_sync(0xffffffffu, m, 2));
        if ((lane & 3) == 0) {
            g_BMIN[rowg[r] * 64 + cblk] = m;         // unique writer per (row, cblk)
            atomicMin(&g_row1[rowg[r]], m);
        }
    }
}

// ---------------- round 1: exact keyB repair + best assembly ----------------
__global__ __launch_bounds__(256) void round1_kernel(const float* __restrict__ batch,
                                                     const float* __restrict__ output) {
    int i = blockIdx.x * 256 + threadIdx.x;
    int a = (int)(g_amin[i] & 0xFFFu);

    const float4* pb = (const float4*)(output + (size_t)i * DIMK);
    const float4* pa = (const float4*)(batch  + (size_t)a * DIMK);
    float s = 0.f;
    #pragma unroll
    for (int q = 0; q < 32; q++) {
        float4 vb = pb[q], va = pa[q];
        float dx = vb.x - va.x, dy = vb.y - va.y, dz = vb.z - va.z, dw = vb.w - va.w;
        s += dx * dx + dy * dy + dz * dz + dw * dw;
    }
    unsigned d2b = __float_as_uint(s);
    g_key2min[i] = d2b;
    g_keyB[i]    = sqrtf(s);

    unsigned b32 = g_row1[i];
    unsigned j  = b32 & 0xFFFu;
    unsigned tw = b32 >> 12;
    unsigned lo = min((unsigned)i, j), hi = max((unsigned)i, j);
    ull kb = ((ull)tw << 26) | ((ull)lo << 13) | hi;

    unsigned tws = d2b >> 12;
    ull ksup = ((ull)tws << 26) | ((ull)(unsigned)i << 13) | SUPER;

    g_best[i] = min(kb, ksup);

    ull w = ksup;
    #pragma unroll
    for (int o = 16; o; o >>= 1) w = min(w, __shfl_xor_sync(0xffffffffu, w, o));
    if ((threadIdx.x & 31) == 0) atomicMin(&g_best[SUPER], w);
}

// ---------------- persistent Boruvka ----------------
__device__ __forceinline__ void grid_sync() {
    __syncthreads();
    if (threadIdx.x == 0) {
        __threadfence();
        unsigned gen = g_barphase;
        if (atomicAdd(&g_barcnt, 1u) == (unsigned)gridDim.x - 1u) {
            g_barcnt = 0u;
            __threadfence();
            g_barphase = gen + 1u;
        } else {
            while (g_barphase == gen) { __nanosleep(32); }
        }
    }
    __syncthreads();
}

// hierarchical scan: warp per row; examine only blocks whose bmin beats running best
__device__ void scan_rows(int* sC, ull* sSup) {
    const int tid = threadIdx.x;
    for (int x = tid; x < NN; x += 256) sC[x] = __ldcg(&g_comp[x]);
    __syncthreads();

    const int warp = tid >> 5, lane = tid & 31;
    const int csup = sC[SUPER];

    ull mySup = ULLMAX;
    for (int i = blockIdx.x * 8 + warp; i < NB; i += NBLK * 8) {
        const int cu = sC[i];
        uint2 bm = *(const uint2*)&g_BMIN[i * 64 + lane * 2];
        unsigned b0 = bm.x, b1 = bm.y;
        unsigned best = 0xFFFFFFFFu;

        for (int it = 0; it < 64; it++) {
            unsigned m = __reduce_min_sync(0xffffffffu, min(b0, b1));
            if (m >= best) break;
            unsigned cand = (b0 == m) ? (unsigned)(lane * 2)
                          : ((b1 == m) ? (unsigned)(lane * 2 + 1) : 0xFFFFu);
            unsigned blk = __reduce_min_sync(0xffffffffu, cand);
            // examine block blk (64 entries, comp-filtered)
            uint2 kv = *(const uint2*)&g_KEY[(size_t)i * NB + blk * 64 + lane * 2];
            unsigned e = 0xFFFFFFFFu;
            if (sC[kv.x & 0xFFFu] != cu) e = kv.x;
            if (sC[kv.y & 0xFFFu] != cu) e = min(e, kv.y);
            best = min(best, __reduce_min_sync(0xffffffffu, e));
            if ((unsigned)(lane * 2)     == blk) b0 = 0xFFFFFFFFu;
            if ((unsigned)(lane * 2 + 1) == blk) b1 = 0xFFFFFFFFu;
        }

        if (lane == 0) {
            ull kb = ULLMAX;
            if (best != 0xFFFFFFFFu) {
                unsigned j  = best & 0xFFFu;
                unsigned tw = best >> 12;
                unsigned lo = min((unsigned)i, j), hi = max((unsigned)i, j);
                kb = ((ull)tw << 26) | ((ull)lo << 13) | hi;
            }
            if (cu != csup) {
                unsigned tws = g_key2min[i] >> 12;
                ull ks = ((ull)tws << 26) | ((ull)(unsigned)i << 13) | SUPER;
                kb = min(kb, ks);
                mySup = min(mySup, ks);
            }
            if (kb != ULLMAX) atomicMin(&g_best[cu], kb);
        }
    }
    if (lane == 0) sSup[warp] = mySup;
    __syncthreads();
    if (tid == 0) {
        ull m = ULLMAX;
        #pragma unroll
        for (int w = 0; w < 8; w++) m = min(m, sSup[w]);
        if (m != ULLMAX) atomicMin(&g_best[csup], m);
    }
    __syncthreads();
}

// merge on block 0
__device__ void merge_block(const float* __restrict__ P, float* __restrict__ out,
                            int* sC, int* sT, float* sRed, int* sCnt) {
    const int tid = threadIdx.x, warp = tid >> 5, lane = tid & 31;

    for (int x = tid; x < NN; x += 256) sC[x] = __ldcg(&g_comp[x]);
    __syncthreads();

    for (int x = tid; x < NN; x += 256) {
        int t = -1;
        if (sC[x] == x) {
            ull k = __ldcg(&g_best[x]);
            if (k != ULLMAX) {
                int u  = (int)((k >> 13) & 0x1FFFu);
                int v  = (int)(k & 0x1FFFu);
                int c1 = sC[u], c2 = sC[v];
                t = (c1 == x) ? c2 : c1;
            }
        }
        sT[x] = t;
    }
    __syncthreads();

    float lsum = 0.f;
    for (int x = tid; x < NN; x += 256) {
        int t = sT[x];
        if (t >= 0) {
            ull k = __ldcg(&g_best[x]);
            bool mutual = (__ldcg(&g_best[t]) == k);
            if (!mutual || x < t) {
                int u = (int)((k >> 13) & 0x1FFFu);
                int v = (int)(k & 0x1FFFu);
                float w;
                if (v == SUPER) {
                    w = g_keyB[u];
                } else {
                    const float4* pu = (const float4*)(P + (size_t)u * DIMK);
                    const float4* pv = (const float4*)(P + (size_t)v * DIMK);
                    float s = 0.f;
                    #pragma unroll 8
                    for (int q = 0; q < 32; q++) {
                        float4 a = pu[q], b = pv[q];
                        float dx = a.x - b.x, dy = a.y - b.y, dz = a.z - b.z, dw = a.w - b.w;
                        s += dx * dx + dy * dy + dz * dz + dw * dw;
                    }
                    w = sqrtf(s);
                }
                lsum += w;
            }
            if (!(mutual && x < t)) sC[x] = t;
        }
    }
    #pragma unroll
    for (int o = 16; o; o >>= 1) lsum += __shfl_xor_sync(0xffffffffu, lsum, o);
    if (lane == 0) sRed[warp] = lsum;
    __syncthreads();

    for (int it = 0; it < 13; it++) {
        int v[17];
        #pragma unroll
        for (int q = 0; q < 17; q++) {
            int x = tid + q * 256;
            v[q] = (x < NN) ? sC[sC[x]] : 0;
        }
        __syncthreads();
        #pragma unroll
        for (int q = 0; q < 17; q++) {
            int x = tid + q * 256;
            if (x < NN) sC[x] = v[q];
        }
        __syncthreads();
    }

    int lcnt = 0;
    for (int x = tid; x < NN; x += 256) {
        int c = sC[x];
        g_comp[x] = c;
        lcnt += (c == x);
        g_best[x] = ULLMAX;
    }
    #pragma unroll
    for (int o = 16; o; o >>= 1) lcnt += __shfl_xor_sync(0xffffffffu, lcnt, o);
    if (lane == 0) sCnt[warp] = lcnt;
    __syncthreads();

    if (tid == 0) {
        float rs = 0.f; int cnt = 0;
        #pragma unroll
        for (int w = 0; w < 8; w++) { rs += sRed[w]; cnt += sCnt[w]; }
        g_total += rs;
        if (cnt <= 1) g_done = 1;
        out[0] = g_total;
    }
    __syncthreads();
}

__global__ __launch_bounds__(256, 2) void boruvka_kernel(const float* __restrict__ P,
                                                         float* __restrict__ out) {
    __shared__ __align__(16) int  sA[NN + 3];
    __shared__ __align__(16) int  sB[NN + 3];
    __shared__ ull   sSup[8];
    __shared__ float sRed[8];
    __shared__ int   sCnt[8];

    for (int round = 0; round < 13; round++) {
        if (blockIdx.x == 0) merge_block(P, out, sA, sB, sRed, sCnt);
        grid_sync();
        if (__ldcg(&g_done)) return;
        scan_rows(sA, sSup);
        grid_sync();
    }
}

// ---------------- launch ----------------
extern "C" void kernel_launch(void* const* d_in, const int* in_sizes, int n_in,
                              void* d_out, int out_size)
{
    const float* batch  = (const float*)d_in[0];   // [16384,128]
    const float* output = (const float*)d_in[1];   // [4096,128]
    float* out = (float*)d_out;

    prep_kernel<<<(NA + NB) / 8, 256>>>(batch, output);
    init_kernel<<<16, 1024>>>();

    dim3 g2(NA / 128, NB / 128);
    key_init_kernel<<<g2, 256>>>();

    dim3 g3(NB / 128, NB / 128);
    dbb_kernel<<<g3, 256>>>();

    round1_kernel<<<NB / 256, 256>>>(batch, output);

    boruvka_kernel<<<NBLK, 256>>>(output, out);
}

// round 10
// speedup vs baseline: 1.2395x; 1.2395x over previous
#include <cuda_runtime.h>
#include <cuda_bf16.h>
#include <math_constants.h>

#define NA    4096
#define NB    4096
#define DIMK  128
#define NN    4097
#define SUPER 4096
#define ULLMAX 0xFFFFFFFFFFFFFFFFULL
#define NBLK  296          // persistent grid: 2 blocks/SM resident

typedef unsigned long long ull;

// ---------------- scratch ----------------
__device__ __align__(16) float    g_sqA[NA];
__device__ __align__(16) float    g_sqB[NB];
__device__ __align__(16) float    g_keyB[NB];      // exact sqrt(d^2(b, a*))
__device__ __align__(16) unsigned g_key2min[NB];   // exact fp32 bits of d^2(b, a*)
__device__ __align__(16) unsigned g_amin[NB];      // packed (approx d2 | a idx)
__device__ __align__(16) unsigned g_row1[NB];      // round-1 per-row min packed key
__device__ __align__(16) unsigned g_Abf[NA * 64];  // bf16x2 packed A points
__device__ __align__(16) unsigned g_Bbf[NB * 64];  // bf16x2 packed B points
__device__ __align__(16) unsigned g_BMIN[NB * 64]; // per-row per-64col block min (1MB)
__device__ __align__(16) unsigned g_KEY[(size_t)NB * NB];  // 64MB packed (d2w20|col12)
__device__ int  g_comp[NN];
__device__ ull  g_best[NN];
__device__ float g_total;
__device__ int   g_done;
__device__ unsigned          g_barcnt;
__device__ volatile unsigned g_barphase;

// ---------------- prep: squared norms + bf16x2 pack, one pass ----------------
__global__ __launch_bounds__(256) void prep_kernel(const float* __restrict__ batch,
                                                   const float* __restrict__ output) {
    int row  = blockIdx.x * 8 + (threadIdx.x >> 5);
    int lane = threadIdx.x & 31;
    bool isA = row < NA;
    const float* src = isA ? (batch + (size_t)row * DIMK)
                           : (output + (size_t)(row - NA) * DIMK);
    float4 v = ((const float4*)src)[lane];
    float s = v.x * v.x + v.y * v.y + v.z * v.z + v.w * v.w;

    __nv_bfloat162 b0 = __float22bfloat162_rn(make_float2(v.x, v.y));
    __nv_bfloat162 b1 = __float22bfloat162_rn(make_float2(v.z, v.w));
    uint2 w;
    w.x = *reinterpret_cast<unsigned*>(&b0);
    w.y = *reinterpret_cast<unsigned*>(&b1);
    unsigned* dst = isA ? (g_Abf + (size_t)row * 64) : (g_Bbf + (size_t)(row - NA) * 64);
    *(uint2*)(dst + lane * 2) = w;

    #pragma unroll
    for (int o = 16; o; o >>= 1) s += __shfl_down_sync(0xffffffffu, s, o);
    if (lane == 0) {
        if (isA) g_sqA[row] = s;
        else     g_sqB[row - NA] = s;
    }
}

// ---------------- init ----------------
__global__ __launch_bounds__(1024) void init_kernel() {
    int i = blockIdx.x * blockDim.x + threadIdx.x;
    int stride = gridDim.x * blockDim.x;
    for (int x = i; x < NN; x += stride) { g_comp[x] = x; g_best[x] = ULLMAX; }
    for (int x = i; x < NB; x += stride) { g_row1[x] = 0xFFFFFFFFu; g_amin[x] = 0xFFFFFFFFu; }
    if (i == 0) { g_total = 0.f; g_done = 0; g_barcnt = 0u; }
}

// ---------------- MMA + cp.async helpers ----------------
__device__ __forceinline__ void ldmx4(unsigned addr, unsigned& r0, unsigned& r1,
                                      unsigned& r2, unsigned& r3) {
    asm volatile("ldmatrix.sync.aligned.m8n8.x4.shared.b16 {%0,%1,%2,%3}, [%4];"
                 : "=r"(r0), "=r"(r1), "=r"(r2), "=r"(r3) : "r"(addr));
}
__device__ __forceinline__ void ldmx2(unsigned addr, unsigned& r0, unsigned& r1) {
    asm volatile("ldmatrix.sync.aligned.m8n8.x2.shared.b16 {%0,%1}, [%2];"
                 : "=r"(r0), "=r"(r1) : "r"(addr));
}
__device__ __forceinline__ void mma_bf16(float* c, unsigned a0, unsigned a1,
                                         unsigned a2, unsigned a3,
                                         unsigned b0, unsigned b1) {
    asm volatile("mma.sync.aligned.m16n8k16.row.col.f32.bf16.bf16.f32 "
                 "{%0,%1,%2,%3},{%4,%5,%6,%7},{%8,%9},{%0,%1,%2,%3};"
                 : "+f"(c[0]), "+f"(c[1]), "+f"(c[2]), "+f"(c[3])
                 : "r"(a0), "r"(a1), "r"(a2), "r"(a3), "r"(b0), "r"(b1));
}
__device__ __forceinline__ void cpa16(unsigned dst, const void* src) {
    asm volatile("cp.async.cg.shared.global [%0], [%1], 16;" :: "r"(dst), "l"(src));
}
__device__ __forceinline__ void cpa_commit() { asm volatile("cp.async.commit_group;"); }
template<int N> __device__ __forceinline__ void cpa_wait() {
    asm volatile("cp.async.wait_group %0;" :: "n"(N));
}

// chunk layout: 128 rows x 32 bf16 (4 x 16B groups); phys slot = r*4 + (g ^ (r&3))
__device__ __forceinline__ void load_chunk_async(unsigned sbase,
                                                 const unsigned* __restrict__ gsrc, int kc) {
    int tid = threadIdx.x;
    #pragma unroll
    for (int it = 0; it < 2; it++) {
        int f = tid + it * 256;
        int r = f >> 2, g = f & 3;
        cpa16(sbase + (unsigned)((r * 4 + (g ^ (r & 3))) << 4),
              gsrc + (size_t)r * 64 + kc * 16 + g * 4);
    }
}
__device__ __forceinline__ unsigned chunk_addr(unsigned base, int row, int g) {
    return base + (unsigned)((row * 4 + (g ^ (row & 3))) << 4);
}
__device__ __forceinline__ void afrag(unsigned base, int mt, int s, int lane,
                                      unsigned& a0, unsigned& a1, unsigned& a2, unsigned& a3) {
    int row = mt + (lane & 7) + ((lane >> 3) & 1) * 8;
    int g   = s * 2 + (lane >> 4);
    ldmx4(chunk_addr(base, row, g), a0, a1, a2, a3);
}
__device__ __forceinline__ void bfrag(unsigned base, int nt, int s, int lane,
                                      unsigned& b0, unsigned& b1) {
    int l15 = lane & 15;
    int row = nt + (l15 & 7);
    int g   = s * 2 + ((l15 >> 3) & 1);
    ldmx2(chunk_addr(base, row, g), b0, b1);
}

// double-buffered 128x128x128 bf16 MMA mainloop -> acc
__device__ __forceinline__ void mma_mainloop(unsigned basePu, unsigned baseQu,
                                             const unsigned* gP, const unsigned* gQ,
                                             float acc[2][8][4], int wm, int wn, int lane) {
    load_chunk_async(basePu, gP, 0);
    load_chunk_async(baseQu, gQ, 0);
    cpa_commit();
    #pragma unroll
    for (int kc = 0; kc < 4; kc++) {
        if (kc < 3) {
            unsigned off = (kc & 1) ? 0u : 8192u;
            load_chunk_async(basePu + off, gP, kc + 1);
            load_chunk_async(baseQu + off, gQ, kc + 1);
            cpa_commit();
            cpa_wait<1>();
        } else {
            cpa_wait<0>();
        }
        __syncthreads();
        unsigned off = (kc & 1) ? 8192u : 0u;
        #pragma unroll
        for (int s = 0; s < 2; s++) {
            unsigned a00, a01, a02, a03, a10, a11, a12, a13;
            afrag(basePu + off, wm,      s, lane, a00, a01, a02, a03);
            afrag(basePu + off, wm + 16, s, lane, a10, a11, a12, a13);
            #pragma unroll
            for (int j = 0; j < 8; j++) {
                unsigned b0, b1;
                bfrag(baseQu + off, wn + j * 8, s, lane, b0, b1);
                mma_bf16(acc[0][j], a00, a01, a02, a03, b0, b1);
                mma_bf16(acc[1][j], a10, a11, a12, a13, b0, b1);
            }
        }
        __syncthreads();
    }
}

// ---------------- K2: approx argmin_a d^2(b,a) ----------------
__global__ __launch_bounds__(256) void key_init_kernel()
{
    __shared__ __align__(16) uint4 sP[2][512];
    __shared__ __align__(16) uint4 sQ[2][512];
    __shared__ float sSqJ[128];

    const int tid = threadIdx.x, warp = tid >> 5, lane = tid & 31;
    const int m0 = blockIdx.y * 128;       // B rows
    const int n0 = blockIdx.x * 128;       // A cols
    const int wm = (warp & 3) * 32;
    const int wn = (warp >> 2) * 64;

    if (tid < 128) sSqJ[tid] = g_sqA[n0 + tid];

    unsigned basePu = (unsigned)__cvta_generic_to_shared(sP);
    unsigned baseQu = (unsigned)__cvta_generic_to_shared(sQ);

    float acc[2][8][4];
    #pragma unroll
    for (int mi = 0; mi < 2; mi++)
        #pragma unroll
        for (int j = 0; j < 8; j++)
            #pragma unroll
            for (int e = 0; e < 4; e++) acc[mi][j][e] = 0.f;

    mma_mainloop(basePu, baseQu, g_Bbf + (size_t)m0 * 64, g_Abf + (size_t)n0 * 64,
                 acc, wm, wn, lane);

    const int mlo = lane >> 2, ne = (lane & 3) * 2;
    float sqi[4];
    #pragma unroll
    for (int mi = 0; mi < 2; mi++) {
        sqi[mi * 2 + 0] = g_sqB[m0 + wm + mi * 16 + mlo];
        sqi[mi * 2 + 1] = g_sqB[m0 + wm + mi * 16 + 8 + mlo];
    }
    unsigned rmin[4] = {0xFFFFFFFFu, 0xFFFFFFFFu, 0xFFFFFFFFu, 0xFFFFFFFFu};
    #pragma unroll
    for (int mi = 0; mi < 2; mi++) {
        #pragma unroll
        for (int j = 0; j < 8; j++) {
            int nl = wn + j * 8 + ne;
            float sq0 = sSqJ[nl], sq1 = sSqJ[nl + 1];
            unsigned aj0 = (unsigned)(n0 + nl), aj1 = aj0 + 1;
            float d2;
            d2 = fmaxf(sqi[mi*2] + sq0 - 2.f * acc[mi][j][0], 0.f);
            rmin[mi*2]   = min(rmin[mi*2],   (__float_as_uint(d2) & 0xFFFFF000u) | aj0);
            d2 = fmaxf(sqi[mi*2] + sq1 - 2.f * acc[mi][j][1], 0.f);
            rmin[mi*2]   = min(rmin[mi*2],   (__float_as_uint(d2) & 0xFFFFF000u) | aj1);
            d2 = fmaxf(sqi[mi*2+1] + sq0 - 2.f * acc[mi][j][2], 0.f);
            rmin[mi*2+1] = min(rmin[mi*2+1], (__float_as_uint(d2) & 0xFFFFF000u) | aj0);
            d2 = fmaxf(sqi[mi*2+1] + sq1 - 2.f * acc[mi][j][3], 0.f);
            rmin[mi*2+1] = min(rmin[mi*2+1], (__float_as_uint(d2) & 0xFFFFF000u) | aj1);
        }
    }
    #pragma unroll
    for (int r = 0; r < 4; r++) {
        unsigned m = rmin[r];
        m = min(m, __shfl_xor_sync(0xffffffffu, m, 1));
        m = min(m, __shfl_xor_sync(0xffffffffu, m, 2));
        if ((lane & 3) == 0) {
            int row = m0 + wm + (r >> 1) * 16 + ((r & 1) ? 8 : 0) + mlo;
            atomicMin(&g_amin[row], m);
        }
    }
}

// ---------------- K3: packed d^2 key matrix + per-64col block mins ----------------
__global__ __launch_bounds__(256) void dbb_kernel()
{
    __shared__ __align__(16) uint4 sP[2][512];
    __shared__ __align__(16) uint4 sQ[2][512];
    __shared__ float sSqJ[128];

    const int tid = threadIdx.x, warp = tid >> 5, lane = tid & 31;
    const int m0 = blockIdx.y * 128;
    const int n0 = blockIdx.x * 128;
    const int wm = (warp & 3) * 32;
    const int wn = (warp >> 2) * 64;

    if (tid < 128) sSqJ[tid] = g_sqB[n0 + tid];

    unsigned basePu = (unsigned)__cvta_generic_to_shared(sP);
    unsigned baseQu = (unsigned)__cvta_generic_to_shared(sQ);

    float acc[2][8][4];
    #pragma unroll
    for (int mi = 0; mi < 2; mi++)
        #pragma unroll
        for (int j = 0; j < 8; j++)
            #pragma unroll
            for (int e = 0; e < 4; e++) acc[mi][j][e] = 0.f;

    mma_mainloop(basePu, baseQu, g_Bbf + (size_t)m0 * 64, g_Bbf + (size_t)n0 * 64,
                 acc, wm, wn, lane);

    const int mlo = lane >> 2, ne = (lane & 3) * 2;
    float sqi[4];
    int rowg[4];
    #pragma unroll
    for (int mi = 0; mi < 2; mi++) {
        rowg[mi*2]   = m0 + wm + mi * 16 + mlo;
        rowg[mi*2+1] = m0 + wm + mi * 16 + 8 + mlo;
        sqi[mi*2]    = g_sqB[rowg[mi*2]];
        sqi[mi*2+1]  = g_sqB[rowg[mi*2+1]];
    }
    unsigned rmin[4] = {0xFFFFFFFFu, 0xFFFFFFFFu, 0xFFFFFFFFu, 0xFFFFFFFFu};
    #pragma unroll
    for (int mi = 0; mi < 2; mi++) {
        #pragma unroll
        for (int j = 0; j < 8; j++) {
            int nl = wn + j * 8 + ne;
            int bj0 = n0 + nl, bj1 = bj0 + 1;
            float sq0 = sSqJ[nl], sq1 = sSqJ[nl + 1];
            #pragma unroll
            for (int h = 0; h < 2; h++) {
                int bi = rowg[mi*2 + h];
                float d20 = fmaxf(sqi[mi*2+h] + sq0 - 2.f * acc[mi][j][h*2+0], 0.f);
                float d21 = fmaxf(sqi[mi*2+h] + sq1 - 2.f * acc[mi][j][h*2+1], 0.f);
                unsigned pk0 = (__float_as_uint(d20) & 0xFFFFF000u) | (unsigned)bj0;
                unsigned pk1 = (__float_as_uint(d21) & 0xFFFFF000u) | (unsigned)bj1;
                if (bj0 != bi) rmin[mi*2+h] = min(rmin[mi*2+h], pk0);
                if (bj1 != bi) rmin[mi*2+h] = min(rmin[mi*2+h], pk1);
                *(uint2*)&g_KEY[(size_t)bi * NB + bj0] = make_uint2(pk0, pk1);
            }
        }
    }
    const int cblk = blockIdx.x * 2 + (warp >> 2);   // 64-col block index
    #pragma unroll
    for (int r = 0; r < 4; r++) {
        unsigned m = rmin[r];
        m = min(m, __shfl_xor_sync(0xffffffffu, m, 1));
        m = min(m, __shfl_xor_sync(0xffffffffu, m, 2));
        if ((lane & 3) == 0) {
            g_BMIN[rowg[r] * 64 + cblk] = m;         // unique writer per (row, cblk)
            atomicMin(&g_row1[rowg[r]], m);
        }
    }
}

// ---------------- round 1: exact keyB repair + best assembly ----------------
__global__ __launch_bounds__(256) void round1_kernel(const float* __restrict__ batch,
                                                     const float* __restrict__ output) {
    int i = blockIdx.x * 256 + threadIdx.x;
    int a = (int)(g_amin[i] & 0xFFFu);

    const float4* pb = (const float4*)(output + (size_t)i * DIMK);
    const float4* pa = (const float4*)(batch  + (size_t)a * DIMK);
    float s = 0.f;
    #pragma unroll
    for (int q = 0; q < 32; q++) {
        float4 vb = pb[q], va = pa[q];
        float dx = vb.x - va.x, dy = vb.y - va.y, dz = vb.z - va.z, dw = vb.w - va.w;
        s += dx * dx + dy * dy + dz * dz + dw * dw;
    }
    unsigned d2b = __float_as_uint(s);
    g_key2min[i] = d2b;
    g_keyB[i]    = sqrtf(s);

    unsigned b32 = g_row1[i];
    unsigned j  = b32 & 0xFFFu;
    unsigned tw = b32 >> 12;
    unsigned lo = min((unsigned)i, j), hi = max((unsigned)i, j);
    ull kb = ((ull)tw << 26) | ((ull)lo << 13) | hi;

    unsigned tws = d2b >> 12;
    ull ksup = ((ull)tws << 26) | ((ull)(unsigned)i << 13) | SUPER;

    g_best[i] = min(kb, ksup);

    ull w = ksup;
    #pragma unroll
    for (int o = 16; o; o >>= 1) w = min(w, __shfl_xor_sync(0xffffffffu, w, o));
    if ((threadIdx.x & 31) == 0) atomicMin(&g_best[SUPER], w);
}

// ---------------- persistent Boruvka ----------------
__device__ __forceinline__ void grid_sync() {
    __syncthreads();
    if (threadIdx.x == 0) {
        __threadfence();
        unsigned gen = g_barphase;
        if (atomicAdd(&g_barcnt, 1u) == (unsigned)gridDim.x - 1u) {
            g_barcnt = 0u;
            __threadfence();
            g_barphase = gen + 1u;
        } else {
            while (g_barphase == gen) { __nanosleep(32); }
        }
    }
    __syncthreads();
}

// scan: warp per row; prune blocks whose bmin tw strictly exceeds
// min(own supernode-edge tw, current component-best tw). Exact: g_best[cu] is
// monotone and final comp key tw <= bound, so pruned (strictly greater) edges
// can never become the component minimum; equal-tw blocks are examined.
__device__ void scan_rows(int* sC, ull* sSup) {
    const int tid = threadIdx.x;
    for (int x = tid; x < NN; x += 256) sC[x] = __ldcg(&g_comp[x]);
    __syncthreads();

    const int warp = tid >> 5, lane = tid & 31;
    const int csup = sC[SUPER];

    ull mySup = ULLMAX;
    for (int i = blockIdx.x * 8 + warp; i < NB; i += NBLK * 8) {
        const int cu = sC[i];

        // a-priori bound (20-bit tw)
        unsigned ksb   = g_key2min[i] >> 12;              // own supernode edge tw
        ull      bu    = __ldcg(&g_best[cu]);
        unsigned btw   = (unsigned)min(bu >> 26, (ull)0xFFFFFu);
        unsigned bound = min(btw, ksb);

        uint2 bm = *(const uint2*)&g_BMIN[i * 64 + lane * 2];
        unsigned m0 = __ballot_sync(0xffffffffu, (bm.x >> 12) <= bound);
        unsigned m1 = __ballot_sync(0xffffffffu, (bm.y >> 12) <= bound);
        ull mask = (ull)m0 | ((ull)m1 << 32);

        unsigned e = 0xFFFFFFFFu;
        const unsigned* rowp = g_KEY + (size_t)i * NB;
        while (mask) {
            int bit = __ffsll((long long)mask) - 1;
            mask &= mask - 1;
            int blk = (bit < 32) ? (bit * 2) : ((bit - 32) * 2 + 1);
            uint2 kv = *(const uint2*)&rowp[blk * 64 + lane * 2];
            if (sC[kv.x & 0xFFFu] != cu) e = min(e, kv.x);
            if (sC[kv.y & 0xFFFu] != cu) e = min(e, kv.y);
        }
        unsigned best = __reduce_min_sync(0xffffffffu, e);

        if (lane == 0) {
            ull kb = ULLMAX;
            if (best != 0xFFFFFFFFu) {
                unsigned j  = best & 0xFFFu;
                unsigned tw = best >> 12;
                unsigned lo = min((unsigned)i, j), hi = max((unsigned)i, j);
                kb = ((ull)tw << 26) | ((ull)lo << 13) | hi;
            }
            if (cu != csup) {
                ull ks = ((ull)ksb << 26) | ((ull)(unsigned)i << 13) | SUPER;
                kb = min(kb, ks);
                mySup = min(mySup, ks);
            }
            if (kb != ULLMAX) atomicMin(&g_best[cu], kb);
        }
    }
    if (lane == 0) sSup[warp] = mySup;
    __syncthreads();
    if (tid == 0) {
        ull m = ULLMAX;
        #pragma unroll
        for (int w = 0; w < 8; w++) m = min(m, sSup[w]);
        if (m != ULLMAX) atomicMin(&g_best[csup], m);
    }
    __syncthreads();
}

// merge on block 0
__device__ void merge_block(const float* __restrict__ P, float* __restrict__ out,
                            int* sC, int* sT, float* sRed, int* sCnt) {
    const int tid = threadIdx.x, warp = tid >> 5, lane = tid & 31;

    for (int x = tid; x < NN; x += 256) sC[x] = __ldcg(&g_comp[x]);
    __syncthreads();

    for (int x = tid; x < NN; x += 256) {
        int t = -1;
        if (sC[x] == x) {
            ull k = __ldcg(&g_best[x]);
            if (k != ULLMAX) {
                int u  = (int)((k >> 13) & 0x1FFFu);
                int v  = (int)(k & 0x1FFFu);
                int c1 = sC[u], c2 = sC[v];
                t = (c1 == x) ? c2 : c1;
            }
        }
        sT[x] = t;
    }
    __syncthreads();

    float lsum = 0.f;
    for (int x = tid; x < NN; x += 256) {
        int t = sT[x];
        if (t >= 0) {
            ull k = __ldcg(&g_best[x]);
            bool mutual = (__ldcg(&g_best[t]) == k);
            if (!mutual || x < t) {
                int u = (int)((k >> 13) & 0x1FFFu);
                int v = (int)(k & 0x1FFFu);
                float w;
                if (v == SUPER) {
                    w = g_keyB[u];
                } else {
                    const float4* pu = (const float4*)(P + (size_t)u * DIMK);
                    const float4* pv = (const float4*)(P + (size_t)v * DIMK);
                    float s = 0.f;
                    #pragma unroll 8
                    for (int q = 0; q < 32; q++) {
                        float4 a = pu[q], b = pv[q];
                        float dx = a.x - b.x, dy = a.y - b.y, dz = a.z - b.z, dw = a.w - b.w;
                        s += dx * dx + dy * dy + dz * dz + dw * dw;
                    }
                    w = sqrtf(s);
                }
                lsum += w;
            }
            if (!(mutual && x < t)) sC[x] = t;
        }
    }
    #pragma unroll
    for (int o = 16; o; o >>= 1) lsum += __shfl_xor_sync(0xffffffffu, lsum, o);
    if (lane == 0) sRed[warp] = lsum;
    __syncthreads();

    for (int it = 0; it < 13; it++) {
        int v[17];
        #pragma unroll
        for (int q = 0; q < 17; q++) {
            int x = tid + q * 256;
            v[q] = (x < NN) ? sC[sC[x]] : 0;
        }
        __syncthreads();
        #pragma unroll
        for (int q = 0; q < 17; q++) {
            int x = tid + q * 256;
            if (x < NN) sC[x] = v[q];
        }
        __syncthreads();
    }

    int lcnt = 0;
    for (int x = tid; x < NN; x += 256) {
        int c = sC[x];
        g_comp[x] = c;
        lcnt += (c == x);
        g_best[x] = ULLMAX;
    }
    #pragma unroll
    for (int o = 16; o; o >>= 1) lcnt += __shfl_xor_sync(0xffffffffu, lcnt, o);
    if (lane == 0) sCnt[warp] = lcnt;
    __syncthreads();

    if (tid == 0) {
        float rs = 0.f; int cnt = 0;
        #pragma unroll
        for (int w = 0; w < 8; w++) { rs += sRed[w]; cnt += sCnt[w]; }
        g_total += rs;
        if (cnt <= 1) g_done = 1;
        out[0] = g_total;
    }
    __syncthreads();
}

__global__ __launch_bounds__(256, 2) void boruvka_kernel(const float* __restrict__ P,
                                                         float* __restrict__ out) {
    __shared__ __align__(16) int  sA[NN + 3];
    __shared__ __align__(16) int  sB[NN + 3];
    __shared__ ull   sSup[8];
    __shared__ float sRed[8];
    __shared__ int   sCnt[8];

    for (int round = 0; round < 13; round++) {
        if (blockIdx.x == 0) merge_block(P, out, sA, sB, sRed, sCnt);
        grid_sync();
        if (__ldcg(&g_done)) return;
        scan_rows(sA, sSup);
        grid_sync();
    }
}

// ---------------- launch ----------------
extern "C" void kernel_launch(void* const* d_in, const int* in_sizes, int n_in,
                              void* d_out, int out_size)
{
    const float* batch  = (const float*)d_in[0];   // [16384,128]
    const float* output = (const float*)d_in[1];   // [4096,128]
    float* out = (float*)d_out;

    prep_kernel<<<(NA + NB) / 8, 256>>>(batch, output);
    init_kernel<<<16, 1024>>>();

    dim3 g2(NA / 128, NB / 128);
    key_init_kernel<<<g2, 256>>>();

    dim3 g3(NB / 128, NB / 128);
    dbb_kernel<<<g3, 256>>>();

    round1_kernel<<<NB / 256, 256>>>(batch, output);

    boruvka_kernel<<<NBLK, 256>>>(output, out);
}

// round 11
// speedup vs baseline: 1.7084x; 1.3783x over previous
#include <cuda_runtime.h>
#include <cuda_bf16.h>
#include <math_constants.h>

#define NA    4096
#define NB    4096
#define DIMK  128
#define NN    4097
#define SUPER 4096
#define ULLMAX 0xFFFFFFFFFFFFFFFFULL
#define NBLK  296          // persistent grid: 2 blocks/SM resident
#define NSEL  (13 * NN)

typedef unsigned long long ull;

// ---------------- scratch ----------------
__device__ __align__(16) float    g_sqA[NA];
__device__ __align__(16) float    g_sqB[NB];
__device__ __align__(16) float    g_keyB[NB];      // exact sqrt(d^2(b, a*))
__device__ __align__(16) unsigned g_key2min[NB];   // exact fp32 bits of d^2(b, a*)
__device__ __align__(16) unsigned g_amin[NB];      // packed (approx d2 | a idx)
__device__ __align__(16) unsigned g_row1[NB];      // round-1 per-row min packed key
__device__ __align__(16) unsigned g_Abf[NA * 64];  // bf16x2 packed A points
__device__ __align__(16) unsigned g_Bbf[NB * 64];  // bf16x2 packed B points
__device__ __align__(16) unsigned g_BMIN[NB * 64]; // per-row per-64col block min (1MB)
__device__ __align__(16) unsigned g_KEY[(size_t)NB * NB];  // 64MB packed (d2w20|col12)
__device__ __align__(16) ull      g_best3[3][NN];  // rotating best buffers
__device__ __align__(16) unsigned g_sel[NSEL];     // per (round,root) selected edge (u13|v13)
__device__ __align__(16) float    g_ew[NSEL];      // per-slot exact weight
__device__ unsigned          g_barcnt;             // 0 after every completed barrier
__device__ volatile unsigned g_barphase;

// ---------------- prep: norms + bf16x2 pack + all state init ----------------
__global__ __launch_bounds__(256) void prep_kernel(const float* __restrict__ batch,
                                                   const float* __restrict__ output) {
    int row  = blockIdx.x * 8 + (threadIdx.x >> 5);
    int lane = threadIdx.x & 31;
    bool isA = row < NA;
    const float* src = isA ? (batch + (size_t)row * DIMK)
                           : (output + (size_t)(row - NA) * DIMK);
    float4 v = ((const float4*)src)[lane];
    float s = v.x * v.x + v.y * v.y + v.z * v.z + v.w * v.w;

    __nv_bfloat162 b0 = __float22bfloat162_rn(make_float2(v.x, v.y));
    __nv_bfloat162 b1 = __float22bfloat162_rn(make_float2(v.z, v.w));
    uint2 w;
    w.x = *reinterpret_cast<unsigned*>(&b0);
    w.y = *reinterpret_cast<unsigned*>(&b1);
    unsigned* dst = isA ? (g_Abf + (size_t)row * 64) : (g_Bbf + (size_t)(row - NA) * 64);
    *(uint2*)(dst + lane * 2) = w;

    #pragma unroll
    for (int o = 16; o; o >>= 1) s += __shfl_down_sync(0xffffffffu, s, o);
    if (lane == 0) {
        if (isA) g_sqA[row] = s;
        else     g_sqB[row - NA] = s;
    }

    // fused state init (grid = 1024x256 = 262144 threads)
    int gid = blockIdx.x * 256 + threadIdx.x;
    if (gid < NN) {
        g_best3[0][gid] = ULLMAX;
        g_best3[1][gid] = ULLMAX;
        g_best3[2][gid] = ULLMAX;
    }
    if (gid < NB) { g_row1[gid] = 0xFFFFFFFFu; g_amin[gid] = 0xFFFFFFFFu; }
    for (int t = gid; t < NSEL; t += 262144) g_sel[t] = 0xFFFFFFFFu;
}

// ---------------- MMA + cp.async helpers ----------------
__device__ __forceinline__ void ldmx4(unsigned addr, unsigned& r0, unsigned& r1,
                                      unsigned& r2, unsigned& r3) {
    asm volatile("ldmatrix.sync.aligned.m8n8.x4.shared.b16 {%0,%1,%2,%3}, [%4];"
                 : "=r"(r0), "=r"(r1), "=r"(r2), "=r"(r3) : "r"(addr));
}
__device__ __forceinline__ void ldmx2(unsigned addr, unsigned& r0, unsigned& r1) {
    asm volatile("ldmatrix.sync.aligned.m8n8.x2.shared.b16 {%0,%1}, [%2];"
                 : "=r"(r0), "=r"(r1) : "r"(addr));
}
__device__ __forceinline__ void mma_bf16(float* c, unsigned a0, unsigned a1,
                                         unsigned a2, unsigned a3,
                                         unsigned b0, unsigned b1) {
    asm volatile("mma.sync.aligned.m16n8k16.row.col.f32.bf16.bf16.f32 "
                 "{%0,%1,%2,%3},{%4,%5,%6,%7},{%8,%9},{%0,%1,%2,%3};"
                 : "+f"(c[0]), "+f"(c[1]), "+f"(c[2]), "+f"(c[3])
                 : "r"(a0), "r"(a1), "r"(a2), "r"(a3), "r"(b0), "r"(b1));
}
__device__ __forceinline__ void cpa16(unsigned dst, const void* src) {
    asm volatile("cp.async.cg.shared.global [%0], [%1], 16;" :: "r"(dst), "l"(src));
}
__device__ __forceinline__ void cpa_commit() { asm volatile("cp.async.commit_group;"); }
template<int N> __device__ __forceinline__ void cpa_wait() {
    asm volatile("cp.async.wait_group %0;" :: "n"(N));
}

__device__ __forceinline__ void load_chunk_async(unsigned sbase,
                                                 const unsigned* __restrict__ gsrc, int kc) {
    int tid = threadIdx.x;
    #pragma unroll
    for (int it = 0; it < 2; it++) {
        int f = tid + it * 256;
        int r = f >> 2, g = f & 3;
        cpa16(sbase + (unsigned)((r * 4 + (g ^ (r & 3))) << 4),
              gsrc + (size_t)r * 64 + kc * 16 + g * 4);
    }
}
__device__ __forceinline__ unsigned chunk_addr(unsigned base, int row, int g) {
    return base + (unsigned)((row * 4 + (g ^ (row & 3))) << 4);
}
__device__ __forceinline__ void afrag(unsigned base, int mt, int s, int lane,
                                      unsigned& a0, unsigned& a1, unsigned& a2, unsigned& a3) {
    int row = mt + (lane & 7) + ((lane >> 3) & 1) * 8;
    int g   = s * 2 + (lane >> 4);
    ldmx4(chunk_addr(base, row, g), a0, a1, a2, a3);
}
__device__ __forceinline__ void bfrag(unsigned base, int nt, int s, int lane,
                                      unsigned& b0, unsigned& b1) {
    int l15 = lane & 15;
    int row = nt + (l15 & 7);
    int g   = s * 2 + ((l15 >> 3) & 1);
    ldmx2(chunk_addr(base, row, g), b0, b1);
}

__device__ __forceinline__ void mma_mainloop(unsigned basePu, unsigned baseQu,
                                             const unsigned* gP, const unsigned* gQ,
                                             float acc[2][8][4], int wm, int wn, int lane) {
    load_chunk_async(basePu, gP, 0);
    load_chunk_async(baseQu, gQ, 0);
    cpa_commit();
    #pragma unroll
    for (int kc = 0; kc < 4; kc++) {
        if (kc < 3) {
            unsigned off = (kc & 1) ? 0u : 8192u;
            load_chunk_async(basePu + off, gP, kc + 1);
            load_chunk_async(baseQu + off, gQ, kc + 1);
            cpa_commit();
            cpa_wait<1>();
        } else {
            cpa_wait<0>();
        }
        __syncthreads();
        unsigned off = (kc & 1) ? 8192u : 0u;
        #pragma unroll
        for (int s = 0; s < 2; s++) {
            unsigned a00, a01, a02, a03, a10, a11, a12, a13;
            afrag(basePu + off, wm,      s, lane, a00, a01, a02, a03);
            afrag(basePu + off, wm + 16, s, lane, a10, a11, a12, a13);
            #pragma unroll
            for (int j = 0; j < 8; j++) {
                unsigned b0, b1;
                bfrag(baseQu + off, wn + j * 8, s, lane, b0, b1);
                mma_bf16(acc[0][j], a00, a01, a02, a03, b0, b1);
                mma_bf16(acc[1][j], a10, a11, a12, a13, b0, b1);
            }
        }
        __syncthreads();
    }
}

// ---------------- fused GEMM kernel: z=0 -> dbb, z=1 -> key_init ----------------
__device__ void key_init_body(uint4* sP, uint4* sQ, float* sSqJ) {
    const int tid = threadIdx.x, warp = tid >> 5, lane = tid & 31;
    const int m0 = blockIdx.y * 128;
    const int n0 = blockIdx.x * 128;
    const int wm = (warp & 3) * 32;
    const int wn = (warp >> 2) * 64;

    if (tid < 128) sSqJ[tid] = g_sqA[n0 + tid];

    unsigned basePu = (unsigned)__cvta_generic_to_shared(sP);
    unsigned baseQu = (unsigned)__cvta_generic_to_shared(sQ);

    float acc[2][8][4];
    #pragma unroll
    for (int mi = 0; mi < 2; mi++)
        #pragma unroll
        for (int j = 0; j < 8; j++)
            #pragma unroll
            for (int e = 0; e < 4; e++) acc[mi][j][e] = 0.f;

    mma_mainloop(basePu, baseQu, g_Bbf + (size_t)m0 * 64, g_Abf + (size_t)n0 * 64,
                 acc, wm, wn, lane);

    const int mlo = lane >> 2, ne = (lane & 3) * 2;
    float sqi[4];
    #pragma unroll
    for (int mi = 0; mi < 2; mi++) {
        sqi[mi * 2 + 0] = g_sqB[m0 + wm + mi * 16 + mlo];
        sqi[mi * 2 + 1] = g_sqB[m0 + wm + mi * 16 + 8 + mlo];
    }
    unsigned rmin[4] = {0xFFFFFFFFu, 0xFFFFFFFFu, 0xFFFFFFFFu, 0xFFFFFFFFu};
    #pragma unroll
    for (int mi = 0; mi < 2; mi++) {
        #pragma unroll
        for (int j = 0; j < 8; j++) {
            int nl = wn + j * 8 + ne;
            float sq0 = sSqJ[nl], sq1 = sSqJ[nl + 1];
            unsigned aj0 = (unsigned)(n0 + nl), aj1 = aj0 + 1;
            float d2;
            d2 = fmaxf(sqi[mi*2] + sq0 - 2.f * acc[mi][j][0], 0.f);
            rmin[mi*2]   = min(rmin[mi*2],   (__float_as_uint(d2) & 0xFFFFF000u) | aj0);
            d2 = fmaxf(sqi[mi*2] + sq1 - 2.f * acc[mi][j][1], 0.f);
            rmin[mi*2]   = min(rmin[mi*2],   (__float_as_uint(d2) & 0xFFFFF000u) | aj1);
            d2 = fmaxf(sqi[mi*2+1] + sq0 - 2.f * acc[mi][j][2], 0.f);
            rmin[mi*2+1] = min(rmin[mi*2+1], (__float_as_uint(d2) & 0xFFFFF000u) | aj0);
            d2 = fmaxf(sqi[mi*2+1] + sq1 - 2.f * acc[mi][j][3], 0.f);
            rmin[mi*2+1] = min(rmin[mi*2+1], (__float_as_uint(d2) & 0xFFFFF000u) | aj1);
        }
    }
    #pragma unroll
    for (int r = 0; r < 4; r++) {
        unsigned m = rmin[r];
        m = min(m, __shfl_xor_sync(0xffffffffu, m, 1));
        m = min(m, __shfl_xor_sync(0xffffffffu, m, 2));
        if ((lane & 3) == 0) {
            int row = m0 + wm + (r >> 1) * 16 + ((r & 1) ? 8 : 0) + mlo;
            atomicMin(&g_amin[row], m);
        }
    }
}

__device__ void dbb_body(uint4* sP, uint4* sQ, float* sSqJ) {
    const int tid = threadIdx.x, warp = tid >> 5, lane = tid & 31;
    const int m0 = blockIdx.y * 128;
    const int n0 = blockIdx.x * 128;
    const int wm = (warp & 3) * 32;
    const int wn = (warp >> 2) * 64;

    if (tid < 128) sSqJ[tid] = g_sqB[n0 + tid];

    unsigned basePu = (unsigned)__cvta_generic_to_shared(sP);
    unsigned baseQu = (unsigned)__cvta_generic_to_shared(sQ);

    float acc[2][8][4];
    #pragma unroll
    for (int mi = 0; mi < 2; mi++)
        #pragma unroll
        for (int j = 0; j < 8; j++)
            #pragma unroll
            for (int e = 0; e < 4; e++) acc[mi][j][e] = 0.f;

    mma_mainloop(basePu, baseQu, g_Bbf + (size_t)m0 * 64, g_Bbf + (size_t)n0 * 64,
                 acc, wm, wn, lane);

    const int mlo = lane >> 2, ne = (lane & 3) * 2;
    float sqi[4];
    int rowg[4];
    #pragma unroll
    for (int mi = 0; mi < 2; mi++) {
        rowg[mi*2]   = m0 + wm + mi * 16 + mlo;
        rowg[mi*2+1] = m0 + wm + mi * 16 + 8 + mlo;
        sqi[mi*2]    = g_sqB[rowg[mi*2]];
        sqi[mi*2+1]  = g_sqB[rowg[mi*2+1]];
    }
    unsigned rmin[4] = {0xFFFFFFFFu, 0xFFFFFFFFu, 0xFFFFFFFFu, 0xFFFFFFFFu};
    #pragma unroll
    for (int mi = 0; mi < 2; mi++) {
        #pragma unroll
        for (int j = 0; j < 8; j++) {
            int nl = wn + j * 8 + ne;
            int bj0 = n0 + nl, bj1 = bj0 + 1;
            float sq0 = sSqJ[nl], sq1 = sSqJ[nl + 1];
            #pragma unroll
            for (int h = 0; h < 2; h++) {
                int bi = rowg[mi*2 + h];
                float d20 = fmaxf(sqi[mi*2+h] + sq0 - 2.f * acc[mi][j][h*2+0], 0.f);
                float d21 = fmaxf(sqi[mi*2+h] + sq1 - 2.f * acc[mi][j][h*2+1], 0.f);
                unsigned pk0 = (__float_as_uint(d20) & 0xFFFFF000u) | (unsigned)bj0;
                unsigned pk1 = (__float_as_uint(d21) & 0xFFFFF000u) | (unsigned)bj1;
                if (bj0 != bi) rmin[mi*2+h] = min(rmin[mi*2+h], pk0);
                if (bj1 != bi) rmin[mi*2+h] = min(rmin[mi*2+h], pk1);
                *(uint2*)&g_KEY[(size_t)bi * NB + bj0] = make_uint2(pk0, pk1);
            }
        }
    }
    const int cblk = blockIdx.x * 2 + (warp >> 2);
    #pragma unroll
    for (int r = 0; r < 4; r++) {
        unsigned m = rmin[r];
        m = min(m, __shfl_xor_sync(0xffffffffu, m, 1));
        m = min(m, __shfl_xor_sync(0xffffffffu, m, 2));
        if ((lane & 3) == 0) {
            g_BMIN[rowg[r] * 64 + cblk] = m;
            atomicMin(&g_row1[rowg[r]], m);
        }
    }
}

__global__ __launch_bounds__(256, 2) void gemm_kernel() {
    __shared__ __align__(16) uint4 sP[2][512];
    __shared__ __align__(16) uint4 sQ[2][512];
    __shared__ float sSqJ[128];
    if (blockIdx.z == 0) dbb_body(&sP[0][0], &sQ[0][0], sSqJ);
    else                 key_init_body(&sP[0][0], &sQ[0][0], sSqJ);
}

// ---------------- round 1: exact keyB repair + best assembly (-> buf 2) ----------------
__global__ __launch_bounds__(256) void round1_kernel(const float* __restrict__ batch,
                                                     const float* __restrict__ output) {
    int i = blockIdx.x * 256 + threadIdx.x;
    int a = (int)(g_amin[i] & 0xFFFu);

    const float4* pb = (const float4*)(output + (size_t)i * DIMK);
    const float4* pa = (const float4*)(batch  + (size_t)a * DIMK);
    float s = 0.f;
    #pragma unroll
    for (int q = 0; q < 32; q++) {
        float4 vb = pb[q], va = pa[q];
        float dx = vb.x - va.x, dy = vb.y - va.y, dz = vb.z - va.z, dw = vb.w - va.w;
        s += dx * dx + dy * dy + dz * dz + dw * dw;
    }
    unsigned d2b = __float_as_uint(s);
    g_key2min[i] = d2b;
    g_keyB[i]    = sqrtf(s);

    unsigned b32 = g_row1[i];
    unsigned j  = b32 & 0xFFFu;
    unsigned tw = b32 >> 12;
    unsigned lo = min((unsigned)i, j), hi = max((unsigned)i, j);
    ull kb = ((ull)tw << 26) | ((ull)lo << 13) | hi;

    unsigned tws = d2b >> 12;
    ull ksup = ((ull)tws << 26) | ((ull)(unsigned)i << 13) | SUPER;

    g_best3[2][i] = min(kb, ksup);

    ull w = ksup;
    #pragma unroll
    for (int o = 16; o; o >>= 1) w = min(w, __shfl_xor_sync(0xffffffffu, w, o));
    if ((threadIdx.x & 31) == 0) atomicMin(&g_best3[2][SUPER], w);
}

// ---------------- persistent Boruvka ----------------
__device__ __forceinline__ void grid_sync() {
    __syncthreads();
    if (threadIdx.x == 0) {
        __threadfence();
        unsigned gen = g_barphase;
        if (atomicAdd(&g_barcnt, 1u) == (unsigned)gridDim.x - 1u) {
            g_barcnt = 0u;
            __threadfence();
            g_barphase = gen + 1u;
        } else {
            while (g_barphase == gen) { __nanosleep(32); }
        }
    }
    __syncthreads();
}

// scan: warp per row, a-priori-bound pruning (exact; see round-10 proof)
__device__ void scan_rows(const int* sC, ull* sSup, ull* bestW) {
    const int tid = threadIdx.x, warp = tid >> 5, lane = tid & 31;
    const int csup = sC[SUPER];

    ull mySup = ULLMAX;
    for (int i = blockIdx.x * 8 + warp; i < NB; i += NBLK * 8) {
        const int cu = sC[i];

        unsigned ksb   = g_key2min[i] >> 12;
        ull      bu    = __ldcg(&bestW[cu]);
        unsigned btw   = (unsigned)min(bu >> 26, (ull)0xFFFFFu);
        unsigned bound = min(btw, ksb);

        uint2 bm = *(const uint2*)&g_BMIN[i * 64 + lane * 2];
        unsigned m0 = __ballot_sync(0xffffffffu, (bm.x >> 12) <= bound);
        unsigned m1 = __ballot_sync(0xffffffffu, (bm.y >> 12) <= bound);
        ull mask = (ull)m0 | ((ull)m1 << 32);

        unsigned e = 0xFFFFFFFFu;
        const unsigned* rowp = g_KEY + (size_t)i * NB;
        while (mask) {
            int bit = __ffsll((long long)mask) - 1;
            mask &= mask - 1;
            int blk = (bit < 32) ? (bit * 2) : ((bit - 32) * 2 + 1);
            uint2 kv = *(const uint2*)&rowp[blk * 64 + lane * 2];
            if (sC[kv.x & 0xFFFu] != cu) e = min(e, kv.x);
            if (sC[kv.y & 0xFFFu] != cu) e = min(e, kv.y);
        }
        unsigned best = __reduce_min_sync(0xffffffffu, e);

        if (lane == 0) {
            ull kb = ULLMAX;
            if (best != 0xFFFFFFFFu) {
                unsigned j  = best & 0xFFFu;
                unsigned tw = best >> 12;
                unsigned lo = min((unsigned)i, j), hi = max((unsigned)i, j);
                kb = ((ull)tw << 26) | ((ull)lo << 13) | hi;
            }
            if (cu != csup) {
                ull ks = ((ull)ksb << 26) | ((ull)(unsigned)i << 13) | SUPER;
                kb = min(kb, ks);
                mySup = min(mySup, ks);
            }
            if (kb != ULLMAX) atomicMin(&bestW[cu], kb);
        }
    }
    if (lane == 0) sSup[warp] = mySup;
    __syncthreads();
    if (tid == 0) {
        ull m = ULLMAX;
        #pragma unroll
        for (int w = 0; w < 8; w++) m = min(m, sSup[w]);
        if (m != ULLMAX) atomicMin(&bestW[csup], m);
    }
    __syncthreads();
}

// merge: executed redundantly by ALL blocks (deterministic), block 0 records edges
__device__ int merge_local(const ull* bestR, unsigned* selRow,
                           int* sC, int* sT, int* sCnt) {
    const int tid = threadIdx.x, warp = tid >> 5, lane = tid & 31;

    for (int x = tid; x < NN; x += 256) {
        int t = -1;
        if (sC[x] == x) {
            ull k = __ldcg(&bestR[x]);
            if (k != ULLMAX) {
                int u  = (int)((k >> 13) & 0x1FFFu);
                int v  = (int)(k & 0x1FFFu);
                int c1 = sC[u], c2 = sC[v];
                t = (c1 == x) ? c2 : c1;
            }
        }
        sT[x] = t;
    }
    __syncthreads();

    for (int x = tid; x < NN; x += 256) {
        int t = sT[x];
        if (t >= 0) {
            ull k = __ldcg(&bestR[x]);
            bool mutual = (__ldcg(&bestR[t]) == k);
            if (blockIdx.x == 0 && (!mutual || x < t)) {
                unsigned u = (unsigned)((k >> 13) & 0x1FFFu);
                unsigned v = (unsigned)(k & 0x1FFFu);
                selRow[x] = (u << 13) | v;
            }
            if (!(mutual && x < t)) sC[x] = t;
        }
    }
    __syncthreads();

    for (int it = 0; it < 13; it++) {
        int v[17];
        #pragma unroll
        for (int q = 0; q < 17; q++) {
            int x = tid + q * 256;
            v[q] = (x < NN) ? sC[sC[x]] : 0;
        }
        __syncthreads();
        #pragma unroll
        for (int q = 0; q < 17; q++) {
            int x = tid + q * 256;
            if (x < NN) sC[x] = v[q];
        }
        __syncthreads();
    }

    int lcnt = 0;
    for (int x = tid; x < NN; x += 256) lcnt += (sC[x] == x);
    #pragma unroll
    for (int o = 16; o; o >>= 1) lcnt += __shfl_xor_sync(0xffffffffu, lcnt, o);
    if (lane == 0) sCnt[warp] = lcnt;
    __syncthreads();
    int nc = sCnt[0] + sCnt[1] + sCnt[2] + sCnt[3] +
             sCnt[4] + sCnt[5] + sCnt[6] + sCnt[7];
    __syncthreads();
    return nc;
}

__global__ __launch_bounds__(256, 2) void boruvka_kernel(const float* __restrict__ P,
                                                         float* __restrict__ out) {
    __shared__ __align__(16) int  sC[NN + 3];
    __shared__ __align__(16) int  sT[NN];
    __shared__ ull   sSup[8];
    __shared__ int   sCnt[8];
    __shared__ float sRed[8];

    const int tid = threadIdx.x, warp = tid >> 5, lane = tid & 31;
    for (int x = tid; x < NN; x += 256) sC[x] = x;
    __syncthreads();

    // rounds: merge r reads buf[(r+2)%3]; scan r writes buf[r%3], resets buf[(r+1)%3]
    for (int r = 0; r < 13; r++) {
        int nc = merge_local(g_best3[(r + 2) % 3], g_sel + r * NN, sC, sT, sCnt);
        if (nc <= 1) break;

        ull* bestW = g_best3[r % 3];
        ull* bestZ = g_best3[(r + 1) % 3];
        for (int x = blockIdx.x * 256 + tid; x < NN; x += NBLK * 256) bestZ[x] = ULLMAX;
        scan_rows(sC, sSup, bestW);
        grid_sync();
    }

    // finalize: make block0's g_sel visible, compute weights grid-wide, fixed-order sum
    grid_sync();
    for (int slot = blockIdx.x * 256 + tid; slot < NSEL; slot += NBLK * 256) {
        unsigned s = __ldcg(&g_sel[slot]);
        if (s != 0xFFFFFFFFu) {
            int u = (int)(s >> 13), v = (int)(s & 0x1FFFu);
            float w;
            if (v == SUPER) {
                w = g_keyB[u];
            } else {
                const float4* pu = (const float4*)(P + (size_t)u * DIMK);
                const float4* pv = (const float4*)(P + (size_t)v * DIMK);
                float sum = 0.f;
                #pragma unroll 8
                for (int q = 0; q < 32; q++) {
                    float4 a = pu[q], b = pv[q];
                    float dx = a.x - b.x, dy = a.y - b.y, dz = a.z - b.z, dw = a.w - b.w;
                    sum += dx * dx + dy * dy + dz * dz + dw * dw;
                }
                w = sqrtf(sum);
            }
            g_ew[slot] = w;
        }
    }
    grid_sync();

    if (blockIdx.x == 0) {
        float ls = 0.f;
        for (int slot = tid; slot < NSEL; slot += 256) {
            if (__ldcg(&g_sel[slot]) != 0xFFFFFFFFu) ls += __ldcg(&g_ew[slot]);
        }
        #pragma unroll
        for (int o = 16; o; o >>= 1) ls += __shfl_xor_sync(0xffffffffu, ls, o);
        if (lane == 0) sRed[warp] = ls;
        __syncthreads();
        if (tid == 0) {
            float tot = 0.f;
            #pragma unroll
            for (int w = 0; w < 8; w++) tot += sRed[w];
            out[0] = tot;
        }
    }
}

// ---------------- launch ----------------
extern "C" void kernel_launch(void* const* d_in, const int* in_sizes, int n_in,
                              void* d_out, int out_size)
{
    const float* batch  = (const float*)d_in[0];   // [16384,128]
    const float* output = (const float*)d_in[1];   // [4096,128]
    float* out = (float*)d_out;

    prep_kernel<<<(NA + NB) / 8, 256>>>(batch, output);

    dim3 gg(NB / 128, NB / 128, 2);
    gemm_kernel<<<gg, 256>>>();

    round1_kernel<<<NB / 256, 256>>>(batch, output);

    boruvka_kernel<<<NBLK, 256>>>(output, out);
}

// round 13
// speedup vs baseline: 1.8461x; 1.0806x over previous
#include <cuda_runtime.h>
#include <cuda_bf16.h>
#include <math_constants.h>

#define NA    4096
#define NB    4096
#define DIMK  128
#define NN    4097
#define SUPER 4096
#define ULLMAX 0xFFFFFFFFFFFFFFFFULL
#define NBLK  296          // persistent grid: 2 blocks/SM resident; 296 = 8 * 37
#define NGRP  8
#define GRPSZ 37
#define NSEL  (13 * NN)

typedef unsigned long long ull;

// ---------------- scratch ----------------
__device__ __align__(16) float    g_sqA[NA];
__device__ __align__(16) float    g_sqB[NB];
__device__ __align__(16) float    g_keyB[NB];      // exact sqrt(d^2(b, a*))
__device__ __align__(16) unsigned g_key2min[NB];   // exact fp32 bits of d^2(b, a*)
__device__ __align__(16) unsigned g_amin[NB];      // packed (approx d2 | a idx)
__device__ __align__(16) unsigned g_row1[NB];      // round-1 per-row min packed key
__device__ __align__(16) unsigned g_Abf[NA * 64];  // bf16x2 packed A points
__device__ __align__(16) unsigned g_Bbf[NB * 64];  // bf16x2 packed B points
__device__ __align__(16) unsigned g_BMIN[NB * 64]; // per-row per-64col block min (1MB)
__device__ __align__(16) unsigned g_KEY[(size_t)NB * NB];  // 64MB packed (d2w20|col12)
__device__ __align__(16) ull      g_best3[3][NN];  // rotating best buffers
__device__ __align__(16) unsigned g_sel[NSEL];     // per (round,root) selected edge (u13|v13)
__device__ __align__(16) float    g_ew[NSEL];      // per-slot exact weight
__device__ __align__(128) unsigned g_grpcnt[NGRP][32];  // padded, MONOTONIC group counters
__device__ unsigned          g_mstcnt;                  // monotonic master counter
__device__ volatile unsigned g_barphase;                // monotonic phase

// ---------------- prep: norms + bf16x2 pack + all state init ----------------
__global__ __launch_bounds__(256) void prep_kernel(const float* __restrict__ batch,
                                                   const float* __restrict__ output) {
    int row  = blockIdx.x * 8 + (threadIdx.x >> 5);
    int lane = threadIdx.x & 31;
    bool isA = row < NA;
    const float* src = isA ? (batch + (size_t)row * DIMK)
                           : (output + (size_t)(row - NA) * DIMK);
    float4 v = ((const float4*)src)[lane];
    float s = v.x * v.x + v.y * v.y + v.z * v.z + v.w * v.w;

    __nv_bfloat162 b0 = __float22bfloat162_rn(make_float2(v.x, v.y));
    __nv_bfloat162 b1 = __float22bfloat162_rn(make_float2(v.z, v.w));
    uint2 w;
    w.x = *reinterpret_cast<unsigned*>(&b0);
    w.y = *reinterpret_cast<unsigned*>(&b1);
    unsigned* dst = isA ? (g_Abf + (size_t)row * 64) : (g_Bbf + (size_t)(row - NA) * 64);
    *(uint2*)(dst + lane * 2) = w;

    #pragma unroll
    for (int o = 16; o; o >>= 1) s += __shfl_down_sync(0xffffffffu, s, o);
    if (lane == 0) {
        if (isA) g_sqA[row] = s;
        else     g_sqB[row - NA] = s;
    }

    // fused state init (grid = 1024x256 = 262144 threads)
    int gid = blockIdx.x * 256 + threadIdx.x;
    if (gid < NN) {
        g_best3[0][gid] = ULLMAX;
        g_best3[1][gid] = ULLMAX;
        g_best3[2][gid] = ULLMAX;
    }
    if (gid < NB) { g_row1[gid] = 0xFFFFFFFFu; g_amin[gid] = 0xFFFFFFFFu; }
    if (gid < NGRP)  g_grpcnt[gid][0] = 0u;
    if (gid == NGRP) { g_mstcnt = 0u; g_barphase = 0u; }
    for (int t = gid; t < NSEL; t += 262144) g_sel[t] = 0xFFFFFFFFu;
}

// ---------------- MMA + cp.async helpers ----------------
__device__ __forceinline__ void ldmx4(unsigned addr, unsigned& r0, unsigned& r1,
                                      unsigned& r2, unsigned& r3) {
    asm volatile("ldmatrix.sync.aligned.m8n8.x4.shared.b16 {%0,%1,%2,%3}, [%4];"
                 : "=r"(r0), "=r"(r1), "=r"(r2), "=r"(r3) : "r"(addr));
}
__device__ __forceinline__ void ldmx2(unsigned addr, unsigned& r0, unsigned& r1) {
    asm volatile("ldmatrix.sync.aligned.m8n8.x2.shared.b16 {%0,%1}, [%2];"
                 : "=r"(r0), "=r"(r1) : "r"(addr));
}
__device__ __forceinline__ void mma_bf16(float* c, unsigned a0, unsigned a1,
                                         unsigned a2, unsigned a3,
                                         unsigned b0, unsigned b1) {
    asm volatile("mma.sync.aligned.m16n8k16.row.col.f32.bf16.bf16.f32 "
                 "{%0,%1,%2,%3},{%4,%5,%6,%7},{%8,%9},{%0,%1,%2,%3};"
                 : "+f"(c[0]), "+f"(c[1]), "+f"(c[2]), "+f"(c[3])
                 : "r"(a0), "r"(a1), "r"(a2), "r"(a3), "r"(b0), "r"(b1));
}
__device__ __forceinline__ void cpa16(unsigned dst, const void* src) {
    asm volatile("cp.async.cg.shared.global [%0], [%1], 16;" :: "r"(dst), "l"(src));
}
__device__ __forceinline__ void cpa_commit() { asm volatile("cp.async.commit_group;"); }
template<int N> __device__ __forceinline__ void cpa_wait() {
    asm volatile("cp.async.wait_group %0;" :: "n"(N));
}

__device__ __forceinline__ void load_chunk_async(unsigned sbase,
                                                 const unsigned* __restrict__ gsrc, int kc) {
    int tid = threadIdx.x;
    #pragma unroll
    for (int it = 0; it < 2; it++) {
        int f = tid + it * 256;
        int r = f >> 2, g = f & 3;
        cpa16(sbase + (unsigned)((r * 4 + (g ^ (r & 3))) << 4),
              gsrc + (size_t)r * 64 + kc * 16 + g * 4);
    }
}
__device__ __forceinline__ unsigned chunk_addr(unsigned base, int row, int g) {
    return base + (unsigned)((row * 4 + (g ^ (row & 3))) << 4);
}
__device__ __forceinline__ void afrag(unsigned base, int mt, int s, int lane,
                                      unsigned& a0, unsigned& a1, unsigned& a2, unsigned& a3) {
    int row = mt + (lane & 7) + ((lane >> 3) & 1) * 8;
    int g   = s * 2 + (lane >> 4);
    ldmx4(chunk_addr(base, row, g), a0, a1, a2, a3);
}
__device__ __forceinline__ void bfrag(unsigned base, int nt, int s, int lane,
                                      unsigned& b0, unsigned& b1) {
    int l15 = lane & 15;
    int row = nt + (l15 & 7);
    int g   = s * 2 + ((l15 >> 3) & 1);
    ldmx2(chunk_addr(base, row, g), b0, b1);
}

__device__ __forceinline__ void mma_mainloop(unsigned basePu, unsigned baseQu,
                                             const unsigned* gP, const unsigned* gQ,
                                             float acc[2][8][4], int wm, int wn, int lane) {
    load_chunk_async(basePu, gP, 0);
    load_chunk_async(baseQu, gQ, 0);
    cpa_commit();
    #pragma unroll
    for (int kc = 0; kc < 4; kc++) {
        if (kc < 3) {
            unsigned off = (kc & 1) ? 0u : 8192u;
            load_chunk_async(basePu + off, gP, kc + 1);
            load_chunk_async(baseQu + off, gQ, kc + 1);
            cpa_commit();
            cpa_wait<1>();
        } else {
            cpa_wait<0>();
        }
        __syncthreads();
        unsigned off = (kc & 1) ? 8192u : 0u;
        #pragma unroll
        for (int s = 0; s < 2; s++) {
            unsigned a00, a01, a02, a03, a10, a11, a12, a13;
            afrag(basePu + off, wm,      s, lane, a00, a01, a02, a03);
            afrag(basePu + off, wm + 16, s, lane, a10, a11, a12, a13);
            #pragma unroll
            for (int j = 0; j < 8; j++) {
                unsigned b0, b1;
                bfrag(baseQu + off, wn + j * 8, s, lane, b0, b1);
                mma_bf16(acc[0][j], a00, a01, a02, a03, b0, b1);
                mma_bf16(acc[1][j], a10, a11, a12, a13, b0, b1);
            }
        }
        __syncthreads();
    }
}

// ---------------- fused GEMM kernel: z=0 -> dbb, z=1 -> key_init ----------------
__device__ void key_init_body(uint4* sP, uint4* sQ, float* sSqJ) {
    const int tid = threadIdx.x, warp = tid >> 5, lane = tid & 31;
    const int m0 = blockIdx.y * 128;
    const int n0 = blockIdx.x * 128;
    const int wm = (warp & 3) * 32;
    const int wn = (warp >> 2) * 64;

    if (tid < 128) sSqJ[tid] = g_sqA[n0 + tid];

    unsigned basePu = (unsigned)__cvta_generic_to_shared(sP);
    unsigned baseQu = (unsigned)__cvta_generic_to_shared(sQ);

    float acc[2][8][4];
    #pragma unroll
    for (int mi = 0; mi < 2; mi++)
        #pragma unroll
        for (int j = 0; j < 8; j++)
            #pragma unroll
            for (int e = 0; e < 4; e++) acc[mi][j][e] = 0.f;

    mma_mainloop(basePu, baseQu, g_Bbf + (size_t)m0 * 64, g_Abf + (size_t)n0 * 64,
                 acc, wm, wn, lane);

    const int mlo = lane >> 2, ne = (lane & 3) * 2;
    float sqi[4];
    #pragma unroll
    for (int mi = 0; mi < 2; mi++) {
        sqi[mi * 2 + 0] = g_sqB[m0 + wm + mi * 16 + mlo];
        sqi[mi * 2 + 1] = g_sqB[m0 + wm + mi * 16 + 8 + mlo];
    }
    unsigned rmin[4] = {0xFFFFFFFFu, 0xFFFFFFFFu, 0xFFFFFFFFu, 0xFFFFFFFFu};
    #pragma unroll
    for (int mi = 0; mi < 2; mi++) {
        #pragma unroll
        for (int j = 0; j < 8; j++) {
            int nl = wn + j * 8 + ne;
            float sq0 = sSqJ[nl], sq1 = sSqJ[nl + 1];
            unsigned aj0 = (unsigned)(n0 + nl), aj1 = aj0 + 1;
            float d2;
            d2 = fmaxf(sqi[mi*2] + sq0 - 2.f * acc[mi][j][0], 0.f);
            rmin[mi*2]   = min(rmin[mi*2],   (__float_as_uint(d2) & 0xFFFFF000u) | aj0);
            d2 = fmaxf(sqi[mi*2] + sq1 - 2.f * acc[mi][j][1], 0.f);
            rmin[mi*2]   = min(rmin[mi*2],   (__float_as_uint(d2) & 0xFFFFF000u) | aj1);
            d2 = fmaxf(sqi[mi*2+1] + sq0 - 2.f * acc[mi][j][2], 0.f);
            rmin[mi*2+1] = min(rmin[mi*2+1], (__float_as_uint(d2) & 0xFFFFF000u) | aj0);
            d2 = fmaxf(sqi[mi*2+1] + sq1 - 2.f * acc[mi][j][3], 0.f);
            rmin[mi*2+1] = min(rmin[mi*2+1], (__float_as_uint(d2) & 0xFFFFF000u) | aj1);
        }
    }
    #pragma unroll
    for (int r = 0; r < 4; r++) {
        unsigned m = rmin[r];
        m = min(m, __shfl_xor_sync(0xffffffffu, m, 1));
        m = min(m, __shfl_xor_sync(0xffffffffu, m, 2));
        if ((lane & 3) == 0) {
            int row = m0 + wm + (r >> 1) * 16 + ((r & 1) ? 8 : 0) + mlo;
            atomicMin(&g_amin[row], m);
        }
    }
}

__device__ void dbb_body(uint4* sP, uint4* sQ, float* sSqJ) {
    const int tid = threadIdx.x, warp = tid >> 5, lane = tid & 31;
    const int m0 = blockIdx.y * 128;
    const int n0 = blockIdx.x * 128;
    const int wm = (warp & 3) * 32;
    const int wn = (warp >> 2) * 64;

    if (tid < 128) sSqJ[tid] = g_sqB[n0 + tid];

    unsigned basePu = (unsigned)__cvta_generic_to_shared(sP);
    unsigned baseQu = (unsigned)__cvta_generic_to_shared(sQ);

    float acc[2][8][4];
    #pragma unroll
    for (int mi = 0; mi < 2; mi++)
        #pragma unroll
        for (int j = 0; j < 8; j++)
            #pragma unroll
            for (int e = 0; e < 4; e++) acc[mi][j][e] = 0.f;

    mma_mainloop(basePu, baseQu, g_Bbf + (size_t)m0 * 64, g_Bbf + (size_t)n0 * 64,
                 acc, wm, wn, lane);

    const int mlo = lane >> 2, ne = (lane & 3) * 2;
    float sqi[4];
    int rowg[4];
    #pragma unroll
    for (int mi = 0; mi < 2; mi++) {
        rowg[mi*2]   = m0 + wm + mi * 16 + mlo;
        rowg[mi*2+1] = m0 + wm + mi * 16 + 8 + mlo;
        sqi[mi*2]    = g_sqB[rowg[mi*2]];
        sqi[mi*2+1]  = g_sqB[rowg[mi*2+1]];
    }
    unsigned rmin[4] = {0xFFFFFFFFu, 0xFFFFFFFFu, 0xFFFFFFFFu, 0xFFFFFFFFu};
    #pragma unroll
    for (int mi = 0; mi < 2; mi++) {
        #pragma unroll
        for (int j = 0; j < 8; j++) {
            int nl = wn + j * 8 + ne;
            int bj0 = n0 + nl, bj1 = bj0 + 1;
            float sq0 = sSqJ[nl], sq1 = sSqJ[nl + 1];
            #pragma unroll
            for (int h = 0; h < 2; h++) {
                int bi = rowg[mi*2 + h];
                float d20 = fmaxf(sqi[mi*2+h] + sq0 - 2.f * acc[mi][j][h*2+0], 0.f);
                float d21 = fmaxf(sqi[mi*2+h] + sq1 - 2.f * acc[mi][j][h*2+1], 0.f);
                unsigned pk0 = (__float_as_uint(d20) & 0xFFFFF000u) | (unsigned)bj0;
                unsigned pk1 = (__float_as_uint(d21) & 0xFFFFF000u) | (unsigned)bj1;
                if (bj0 != bi) rmin[mi*2+h] = min(rmin[mi*2+h], pk0);
                if (bj1 != bi) rmin[mi*2+h] = min(rmin[mi*2+h], pk1);
                *(uint2*)&g_KEY[(size_t)bi * NB + bj0] = make_uint2(pk0, pk1);
            }
        }
    }
    const int cblk = blockIdx.x * 2 + (warp >> 2);
    #pragma unroll
    for (int r = 0; r < 4; r++) {
        unsigned m = rmin[r];
        m = min(m, __shfl_xor_sync(0xffffffffu, m, 1));
        m = min(m, __shfl_xor_sync(0xffffffffu, m, 2));
        if ((lane & 3) == 0) {
            g_BMIN[rowg[r] * 64 + cblk] = m;
            atomicMin(&g_row1[rowg[r]], m);
        }
    }
}

__global__ __launch_bounds__(256, 2) void gemm_kernel() {
    __shared__ __align__(16) uint4 sP[2][512];
    __shared__ __align__(16) uint4 sQ[2][512];
    __shared__ float sSqJ[128];
    if (blockIdx.z == 0) dbb_body(&sP[0][0], &sQ[0][0], sSqJ);
    else                 key_init_body(&sP[0][0], &sQ[0][0], sSqJ);
}

// ---------------- round 1: exact keyB repair + best assembly (-> buf 2) ----------------
__global__ __launch_bounds__(256) void round1_kernel(const float* __restrict__ batch,
                                                     const float* __restrict__ output) {
    int i = blockIdx.x * 256 + threadIdx.x;
    int a = (int)(g_amin[i] & 0xFFFu);

    const float4* pb = (const float4*)(output + (size_t)i * DIMK);
    const float4* pa = (const float4*)(batch  + (size_t)a * DIMK);
    float s = 0.f;
    #pragma unroll
    for (int q = 0; q < 32; q++) {
        float4 vb = pb[q], va = pa[q];
        float dx = vb.x - va.x, dy = vb.y - va.y, dz = vb.z - va.z, dw = vb.w - va.w;
        s += dx * dx + dy * dy + dz * dz + dw * dw;
    }
    unsigned d2b = __float_as_uint(s);
    g_key2min[i] = d2b;
    g_keyB[i]    = sqrtf(s);

    unsigned b32 = g_row1[i];
    unsigned j  = b32 & 0xFFFu;
    unsigned tw = b32 >> 12;
    unsigned lo = min((unsigned)i, j), hi = max((unsigned)i, j);
    ull kb = ((ull)tw << 26) | ((ull)lo << 13) | hi;

    unsigned tws = d2b >> 12;
    ull ksup = ((ull)tws << 26) | ((ull)(unsigned)i << 13) | SUPER;

    g_best3[2][i] = min(kb, ksup);

    ull w = ksup;
    #pragma unroll
    for (int o = 16; o; o >>= 1) w = min(w, __shfl_xor_sync(0xffffffffu, w, o));
    if ((threadIdx.x & 31) == 0) atomicMin(&g_best3[2][SUPER], w);
}

// ---------------- persistent Boruvka: MONOTONIC two-level tree barrier ----------------
// No counter resets, no plain stores -> no reset/arrival race. Each block carries a
// local generation index `bar`; group-last for generation k sees ticket k*GRPSZ+GRPSZ-1
// (blocks cannot arrive at generation k+1 before phase k+1 is published).
__device__ __forceinline__ void grid_sync(unsigned& bar) {
    __syncthreads();
    if (threadIdx.x == 0) {
        __threadfence();
        int g = blockIdx.x & (NGRP - 1);
        unsigned t = atomicAdd(&g_grpcnt[g][0], 1u);
        if (t == bar * GRPSZ + (GRPSZ - 1u)) {
            unsigned m = atomicAdd(&g_mstcnt, 1u);
            if (m == bar * NGRP + (NGRP - 1u)) {
                __threadfence();
                g_barphase = bar + 1u;
            }
        }
        while (g_barphase <= bar) { __nanosleep(32); }
    }
    __syncthreads();
    bar++;
}

// scan: warp per row, a-priori-bound pruning (exact; see round-10 proof)
__device__ void scan_rows(const int* sC, ull* sSup, ull* bestW) {
    const int tid = threadIdx.x, warp = tid >> 5, lane = tid & 31;
    const int csup = sC[SUPER];

    ull mySup = ULLMAX;
    for (int i = blockIdx.x * 8 + warp; i < NB; i += NBLK * 8) {
        const int cu = sC[i];

        unsigned ksb   = g_key2min[i] >> 12;
        ull      bu    = __ldcg(&bestW[cu]);
        unsigned btw   = (unsigned)min(bu >> 26, (ull)0xFFFFFu);
        unsigned bound = min(btw, ksb);

        uint2 bm = *(const uint2*)&g_BMIN[i * 64 + lane * 2];
        unsigned m0 = __ballot_sync(0xffffffffu, (bm.x >> 12) <= bound);
        unsigned m1 = __ballot_sync(0xffffffffu, (bm.y >> 12) <= bound);
        ull mask = (ull)m0 | ((ull)m1 << 32);

        unsigned e = 0xFFFFFFFFu;
        const unsigned* rowp = g_KEY + (size_t)i * NB;
        while (mask) {
            int bit = __ffsll((long long)mask) - 1;
            mask &= mask - 1;
            int blk = (bit < 32) ? (bit * 2) : ((bit - 32) * 2 + 1);
            uint2 kv = *(const uint2*)&rowp[blk * 64 + lane * 2];
            if (sC[kv.x & 0xFFFu] != cu) e = min(e, kv.x);
            if (sC[kv.y & 0xFFFu] != cu) e = min(e, kv.y);
        }
        unsigned best = __reduce_min_sync(0xffffffffu, e);

        if (lane == 0) {
            ull kb = ULLMAX;
            if (best != 0xFFFFFFFFu) {
                unsigned j  = best & 0xFFFu;
                unsigned tw = best >> 12;
                unsigned lo = min((unsigned)i, j), hi = max((unsigned)i, j);
                kb = ((ull)tw << 26) | ((ull)lo << 13) | hi;
            }
            if (cu != csup) {
                ull ks = ((ull)ksb << 26) | ((ull)(unsigned)i << 13) | SUPER;
                kb = min(kb, ks);
                mySup = min(mySup, ks);
            }
            if (kb != ULLMAX) atomicMin(&bestW[cu], kb);
        }
    }
    if (lane == 0) sSup[warp] = mySup;
    __syncthreads();
    if (tid == 0) {
        ull m = ULLMAX;
        #pragma unroll
        for (int w = 0; w < 8; w++) m = min(m, sSup[w]);
        if (m != ULLMAX) atomicMin(&bestW[csup], m);
    }
    __syncthreads();
}

// merge: executed redundantly by ALL blocks (deterministic), block 0 records edges
__device__ int merge_local(const ull* bestR, unsigned* selRow,
                           int* sC, int* sT, int* sCnt) {
    const int tid = threadIdx.x, warp = tid >> 5, lane = tid & 31;

    for (int x = tid; x < NN; x += 256) {
        int t = -1;
        if (sC[x] == x) {
            ull k = __ldcg(&bestR[x]);
            if (k != ULLMAX) {
                int u  = (int)((k >> 13) & 0x1FFFu);
                int v  = (int)(k & 0x1FFFu);
                int c1 = sC[u], c2 = sC[v];
                t = (c1 == x) ? c2 : c1;
            }
        }
        sT[x] = t;
    }
    __syncthreads();

    for (int x = tid; x < NN; x += 256) {
        int t = sT[x];
        if (t >= 0) {
            ull k = __ldcg(&bestR[x]);
            bool mutual = (__ldcg(&bestR[t]) == k);
            if (blockIdx.x == 0 && (!mutual || x < t)) {
                unsigned u = (unsigned)((k >> 13) & 0x1FFFu);
                unsigned v = (unsigned)(k & 0x1FFFu);
                selRow[x] = (u << 13) | v;
            }
            if (!(mutual && x < t)) sC[x] = t;
        }
    }
    __syncthreads();

    // pointer jumping with deterministic early exit (identical data in all blocks)
    for (int it = 0; it < 13; it++) {
        int v[17];
        int ch = 0;
        #pragma unroll
        for (int q = 0; q < 17; q++) {
            int x = tid + q * 256;
            if (x < NN) {
                int c = sC[x];
                v[q] = sC[c];
                ch |= (v[q] != c);
            } else v[q] = 0;
        }
        int any = __syncthreads_or(ch);
        if (!any) break;
        #pragma unroll
        for (int q = 0; q < 17; q++) {
            int x = tid + q * 256;
            if (x < NN) sC[x] = v[q];
        }
        __syncthreads();
    }

    int lcnt = 0;
    for (int x = tid; x < NN; x += 256) lcnt += (sC[x] == x);
    #pragma unroll
    for (int o = 16; o; o >>= 1) lcnt += __shfl_xor_sync(0xffffffffu, lcnt, o);
    if (lane == 0) sCnt[warp] = lcnt;
    __syncthreads();
    int nc = sCnt[0] + sCnt[1] + sCnt[2] + sCnt[3] +
             sCnt[4] + sCnt[5] + sCnt[6] + sCnt[7];
    __syncthreads();
    return nc;
}

__global__ __launch_bounds__(256, 2) void boruvka_kernel(const float* __restrict__ P,
                                                         float* __restrict__ out) {
    __shared__ __align__(16) int  sC[NN + 3];
    __shared__ __align__(16) int  sT[NN];
    __shared__ ull   sSup[8];
    __shared__ int   sCnt[8];
    __shared__ float sRed[8];

    const int tid = threadIdx.x, warp = tid >> 5, lane = tid & 31;
    unsigned bar = 0u;
    for (int x = tid; x < NN; x += 256) sC[x] = x;
    __syncthreads();

    // rounds: merge r reads buf[(r+2)%3]; scan r writes buf[r%3], resets buf[(r+1)%3]
    for (int r = 0; r < 13; r++) {
        int nc = merge_local(g_best3[(r + 2) % 3], g_sel + r * NN, sC, sT, sCnt);
        if (nc <= 1) break;

        ull* bestW = g_best3[r % 3];
        ull* bestZ = g_best3[(r + 1) % 3];
        for (int x = blockIdx.x * 256 + tid; x < NN; x += NBLK * 256) bestZ[x] = ULLMAX;
        scan_rows(sC, sSup, bestW);
        grid_sync(bar);
    }

    // finalize: make block0's g_sel visible, compute weights grid-wide, fixed-order sum
    grid_sync(bar);
    for (int slot = blockIdx.x * 256 + tid; slot < NSEL; slot += NBLK * 256) {
        unsigned s = __ldcg(&g_sel[slot]);
        if (s != 0xFFFFFFFFu) {
            int u = (int)(s >> 13), v = (int)(s & 0x1FFFu);
            float w;
            if (v == SUPER) {
                w = g_keyB[u];
            } else {
                const float4* pu = (const float4*)(P + (size_t)u * DIMK);
                const float4* pv = (const float4*)(P + (size_t)v * DIMK);
                float sum = 0.f;
                #pragma unroll 8
                for (int q = 0; q < 32; q++) {
                    float4 a = pu[q], b = pv[q];
                    float dx = a.x - b.x, dy = a.y - b.y, dz = a.z - b.z, dw = a.w - b.w;
                    sum += dx * dx + dy * dy + dz * dz + dw * dw;
                }
                w = sqrtf(sum);
            }
            g_ew[slot] = w;
        }
    }
    grid_sync(bar);

    if (blockIdx.x == 0) {
        float ls = 0.f;
        for (int slot = tid; slot < NSEL; slot += 256) {
            if (__ldcg(&g_sel[slot]) != 0xFFFFFFFFu) ls += __ldcg(&g_ew[slot]);
        }
        #pragma unroll
        for (int o = 16; o; o >>= 1) ls += __shfl_xor_sync(0xffffffffu, ls, o);
        if (lane == 0) sRed[warp] = ls;
        __syncthreads();
        if (tid == 0) {
            float tot = 0.f;
            #pragma unroll
            for (int w = 0; w < 8; w++) tot += sRed[w];
            out[0] = tot;
        }
    }
}

// ---------------- launch ----------------
extern "C" void kernel_launch(void* const* d_in, const int* in_sizes, int n_in,
                              void* d_out, int out_size)
{
    const float* batch  = (const float*)d_in[0];   // [16384,128]
    const float* output = (const float*)d_in[1];   // [4096,128]
    float* out = (float*)d_out;

    prep_kernel<<<(NA + NB) / 8, 256>>>(batch, output);

    dim3 gg(NB / 128, NB / 128, 2);
    gemm_kernel<<<gg, 256>>>();

    round1_kernel<<<NB / 256, 256>>>(batch, output);

    boruvka_kernel<<<NBLK, 256>>>(output, out);
}

// round 14
// speedup vs baseline: 2.0315x; 1.1004x over previous
#include <cuda_runtime.h>
#include <cuda_bf16.h>
#include <math_constants.h>

#define NA    4096
#define NB    4096
#define DIMK  128
#define NN    4097
#define SUPER 4096
#define ULLMAX 0xFFFFFFFFFFFFFFFFULL
#define NBLK  296          // persistent grid: 2 blocks/SM resident; 296 = 8 * 37
#define NGRP  8
#define GRPSZ 37
#define NSEL  (13 * NN)

typedef unsigned long long ull;

// ---------------- scratch ----------------
__device__ __align__(16) float    g_sqA[NA];
__device__ __align__(16) float    g_sqB[NB];
__device__ __align__(16) float    g_keyB[NB];      // exact sqrt(d^2(b, a*))
__device__ __align__(16) unsigned g_key2min[NB];   // exact fp32 bits of d^2(b, a*)
__device__ __align__(16) unsigned g_amin[NB];      // packed (approx d2 | a idx)
__device__ __align__(16) unsigned g_row1[NB];      // round-1 per-row min packed key
__device__ __align__(16) unsigned g_Abf[NA * 64];  // bf16x2 packed A points
__device__ __align__(16) unsigned g_Bbf[NB * 64];  // bf16x2 packed B points
__device__ __align__(16) unsigned g_BMIN[NB * 64]; // per-row per-64col block min (1MB)
__device__ __align__(16) unsigned g_KEY[(size_t)NB * NB];  // 64MB packed (d2w20|col12)
__device__ __align__(16) ull      g_best3[3][NN];  // rotating best buffers
__device__ __align__(16) unsigned g_sel[NSEL];     // per (round,root) selected edge (u13|v13)
__device__ __align__(16) float    g_ew[NSEL + 3];  // per-slot exact weight (0 if unused)
__device__ __align__(128) unsigned g_grpcnt[NGRP][32];  // padded, MONOTONIC group counters
__device__ unsigned          g_mstcnt;                  // monotonic master counter
__device__ volatile unsigned g_barphase;                // monotonic phase

// ---------------- prep: norms + bf16x2 pack + all state init ----------------
__global__ __launch_bounds__(256) void prep_kernel(const float* __restrict__ batch,
                                                   const float* __restrict__ output) {
    int row  = blockIdx.x * 8 + (threadIdx.x >> 5);
    int lane = threadIdx.x & 31;
    bool isA = row < NA;
    const float* src = isA ? (batch + (size_t)row * DIMK)
                           : (output + (size_t)(row - NA) * DIMK);
    float4 v = ((const float4*)src)[lane];
    float s = v.x * v.x + v.y * v.y + v.z * v.z + v.w * v.w;

    __nv_bfloat162 b0 = __float22bfloat162_rn(make_float2(v.x, v.y));
    __nv_bfloat162 b1 = __float22bfloat162_rn(make_float2(v.z, v.w));
    uint2 w;
    w.x = *reinterpret_cast<unsigned*>(&b0);
    w.y = *reinterpret_cast<unsigned*>(&b1);
    unsigned* dst = isA ? (g_Abf + (size_t)row * 64) : (g_Bbf + (size_t)(row - NA) * 64);
    *(uint2*)(dst + lane * 2) = w;

    #pragma unroll
    for (int o = 16; o; o >>= 1) s += __shfl_down_sync(0xffffffffu, s, o);
    if (lane == 0) {
        if (isA) g_sqA[row] = s;
        else     g_sqB[row - NA] = s;
    }

    // fused state init (grid = 1024x256 = 262144 threads)
    int gid = blockIdx.x * 256 + threadIdx.x;
    if (gid < NN) {
        g_best3[0][gid] = ULLMAX;
        g_best3[1][gid] = ULLMAX;
        g_best3[2][gid] = ULLMAX;
    }
    if (gid < NB) { g_row1[gid] = 0xFFFFFFFFu; g_amin[gid] = 0xFFFFFFFFu; }
    if (gid < NGRP)  g_grpcnt[gid][0] = 0u;
    if (gid == NGRP) { g_mstcnt = 0u; g_barphase = 0u; }
    for (int t = gid; t < NSEL; t += 262144) { g_sel[t] = 0xFFFFFFFFu; g_ew[t] = 0.f; }
    if (gid < 3) g_ew[NSEL + gid] = 0.f;
}

// ---------------- MMA + cp.async helpers ----------------
__device__ __forceinline__ void ldmx4(unsigned addr, unsigned& r0, unsigned& r1,
                                      unsigned& r2, unsigned& r3) {
    asm volatile("ldmatrix.sync.aligned.m8n8.x4.shared.b16 {%0,%1,%2,%3}, [%4];"
                 : "=r"(r0), "=r"(r1), "=r"(r2), "=r"(r3) : "r"(addr));
}
__device__ __forceinline__ void ldmx2(unsigned addr, unsigned& r0, unsigned& r1) {
    asm volatile("ldmatrix.sync.aligned.m8n8.x2.shared.b16 {%0,%1}, [%2];"
                 : "=r"(r0), "=r"(r1) : "r"(addr));
}
__device__ __forceinline__ void mma_bf16(float* c, unsigned a0, unsigned a1,
                                         unsigned a2, unsigned a3,
                                         unsigned b0, unsigned b1) {
    asm volatile("mma.sync.aligned.m16n8k16.row.col.f32.bf16.bf16.f32 "
                 "{%0,%1,%2,%3},{%4,%5,%6,%7},{%8,%9},{%0,%1,%2,%3};"
                 : "+f"(c[0]), "+f"(c[1]), "+f"(c[2]), "+f"(c[3])
                 : "r"(a0), "r"(a1), "r"(a2), "r"(a3), "r"(b0), "r"(b1));
}
__device__ __forceinline__ void cpa16(unsigned dst, const void* src) {
    asm volatile("cp.async.cg.shared.global [%0], [%1], 16;" :: "r"(dst), "l"(src));
}
__device__ __forceinline__ void cpa_commit() { asm volatile("cp.async.commit_group;"); }
template<int N> __device__ __forceinline__ void cpa_wait() {
    asm volatile("cp.async.wait_group %0;" :: "n"(N));
}

__device__ __forceinline__ void load_chunk_async(unsigned sbase,
                                                 const unsigned* __restrict__ gsrc, int kc) {
    int tid = threadIdx.x;
    #pragma unroll
    for (int it = 0; it < 2; it++) {
        int f = tid + it * 256;
        int r = f >> 2, g = f & 3;
        cpa16(sbase + (unsigned)((r * 4 + (g ^ (r & 3))) << 4),
              gsrc + (size_t)r * 64 + kc * 16 + g * 4);
    }
}
__device__ __forceinline__ unsigned chunk_addr(unsigned base, int row, int g) {
    return base + (unsigned)((row * 4 + (g ^ (row & 3))) << 4);
}
__device__ __forceinline__ void afrag(unsigned base, int mt, int s, int lane,
                                      unsigned& a0, unsigned& a1, unsigned& a2, unsigned& a3) {
    int row = mt + (lane & 7) + ((lane >> 3) & 1) * 8;
    int g   = s * 2 + (lane >> 4);
    ldmx4(chunk_addr(base, row, g), a0, a1, a2, a3);
}
__device__ __forceinline__ void bfrag(unsigned base, int nt, int s, int lane,
                                      unsigned& b0, unsigned& b1) {
    int l15 = lane & 15;
    int row = nt + (l15 & 7);
    int g   = s * 2 + ((l15 >> 3) & 1);
    ldmx2(chunk_addr(base, row, g), b0, b1);
}

__device__ __forceinline__ void mma_mainloop(unsigned basePu, unsigned baseQu,
                                             const unsigned* gP, const unsigned* gQ,
                                             float acc[2][8][4], int wm, int wn, int lane) {
    load_chunk_async(basePu, gP, 0);
    load_chunk_async(baseQu, gQ, 0);
    cpa_commit();
    #pragma unroll
    for (int kc = 0; kc < 4; kc++) {
        if (kc < 3) {
            unsigned off = (kc & 1) ? 0u : 8192u;
            load_chunk_async(basePu + off, gP, kc + 1);
            load_chunk_async(baseQu + off, gQ, kc + 1);
            cpa_commit();
            cpa_wait<1>();
        } else {
            cpa_wait<0>();
        }
        __syncthreads();
        unsigned off = (kc & 1) ? 8192u : 0u;
        #pragma unroll
        for (int s = 0; s < 2; s++) {
            unsigned a00, a01, a02, a03, a10, a11, a12, a13;
            afrag(basePu + off, wm,      s, lane, a00, a01, a02, a03);
            afrag(basePu + off, wm + 16, s, lane, a10, a11, a12, a13);
            #pragma unroll
            for (int j = 0; j < 8; j++) {
                unsigned b0, b1;
                bfrag(baseQu + off, wn + j * 8, s, lane, b0, b1);
                mma_bf16(acc[0][j], a00, a01, a02, a03, b0, b1);
                mma_bf16(acc[1][j], a10, a11, a12, a13, b0, b1);
            }
        }
        __syncthreads();
    }
}

// ---------------- fused GEMM kernel: z=0 -> dbb, z=1 -> key_init ----------------
__device__ void key_init_body(uint4* sP, uint4* sQ, float* sSqJ) {
    const int tid = threadIdx.x, warp = tid >> 5, lane = tid & 31;
    const int m0 = blockIdx.y * 128;
    const int n0 = blockIdx.x * 128;
    const int wm = (warp & 3) * 32;
    const int wn = (warp >> 2) * 64;

    if (tid < 128) sSqJ[tid] = g_sqA[n0 + tid];

    unsigned basePu = (unsigned)__cvta_generic_to_shared(sP);
    unsigned baseQu = (unsigned)__cvta_generic_to_shared(sQ);

    float acc[2][8][4];
    #pragma unroll
    for (int mi = 0; mi < 2; mi++)
        #pragma unroll
        for (int j = 0; j < 8; j++)
            #pragma unroll
            for (int e = 0; e < 4; e++) acc[mi][j][e] = 0.f;

    mma_mainloop(basePu, baseQu, g_Bbf + (size_t)m0 * 64, g_Abf + (size_t)n0 * 64,
                 acc, wm, wn, lane);

    const int mlo = lane >> 2, ne = (lane & 3) * 2;
    float sqi[4];
    #pragma unroll
    for (int mi = 0; mi < 2; mi++) {
        sqi[mi * 2 + 0] = g_sqB[m0 + wm + mi * 16 + mlo];
        sqi[mi * 2 + 1] = g_sqB[m0 + wm + mi * 16 + 8 + mlo];
    }
    unsigned rmin[4] = {0xFFFFFFFFu, 0xFFFFFFFFu, 0xFFFFFFFFu, 0xFFFFFFFFu};
    #pragma unroll
    for (int mi = 0; mi < 2; mi++) {
        #pragma unroll
        for (int j = 0; j < 8; j++) {
            int nl = wn + j * 8 + ne;
            float sq0 = sSqJ[nl], sq1 = sSqJ[nl + 1];
            unsigned aj0 = (unsigned)(n0 + nl), aj1 = aj0 + 1;
            float d2;
            d2 = fmaxf(sqi[mi*2] + sq0 - 2.f * acc[mi][j][0], 0.f);
            rmin[mi*2]   = min(rmin[mi*2],   (__float_as_uint(d2) & 0xFFFFF000u) | aj0);
            d2 = fmaxf(sqi[mi*2] + sq1 - 2.f * acc[mi][j][1], 0.f);
            rmin[mi*2]   = min(rmin[mi*2],   (__float_as_uint(d2) & 0xFFFFF000u) | aj1);
            d2 = fmaxf(sqi[mi*2+1] + sq0 - 2.f * acc[mi][j][2], 0.f);
            rmin[mi*2+1] = min(rmin[mi*2+1], (__float_as_uint(d2) & 0xFFFFF000u) | aj0);
            d2 = fmaxf(sqi[mi*2+1] + sq1 - 2.f * acc[mi][j][3], 0.f);
            rmin[mi*2+1] = min(rmin[mi*2+1], (__float_as_uint(d2) & 0xFFFFF000u) | aj1);
        }
    }
    #pragma unroll
    for (int r = 0; r < 4; r++) {
        unsigned m = rmin[r];
        m = min(m, __shfl_xor_sync(0xffffffffu, m, 1));
        m = min(m, __shfl_xor_sync(0xffffffffu, m, 2));
        if ((lane & 3) == 0) {
            int row = m0 + wm + (r >> 1) * 16 + ((r & 1) ? 8 : 0) + mlo;
            atomicMin(&g_amin[row], m);
        }
    }
}

__device__ void dbb_body(uint4* sP, uint4* sQ, float* sSqJ) {
    const int tid = threadIdx.x, warp = tid >> 5, lane = tid & 31;
    const int m0 = blockIdx.y * 128;
    const int n0 = blockIdx.x * 128;
    const int wm = (warp & 3) * 32;
    const int wn = (warp >> 2) * 64;

    if (tid < 128) sSqJ[tid] = g_sqB[n0 + tid];

    unsigned basePu = (unsigned)__cvta_generic_to_shared(sP);
    unsigned baseQu = (unsigned)__cvta_generic_to_shared(sQ);

    float acc[2][8][4];
    #pragma unroll
    for (int mi = 0; mi < 2; mi++)
        #pragma unroll
        for (int j = 0; j < 8; j++)
            #pragma unroll
            for (int e = 0; e < 4; e++) acc[mi][j][e] = 0.f;

    mma_mainloop(basePu, baseQu, g_Bbf + (size_t)m0 * 64, g_Bbf + (size_t)n0 * 64,
                 acc, wm, wn, lane);

    const int mlo = lane >> 2, ne = (lane & 3) * 2;
    float sqi[4];
    int rowg[4];
    #pragma unroll
    for (int mi = 0; mi < 2; mi++) {
        rowg[mi*2]   = m0 + wm + mi * 16 + mlo;
        rowg[mi*2+1] = m0 + wm + mi * 16 + 8 + mlo;
        sqi[mi*2]    = g_sqB[rowg[mi*2]];
        sqi[mi*2+1]  = g_sqB[rowg[mi*2+1]];
    }
    unsigned rmin[4] = {0xFFFFFFFFu, 0xFFFFFFFFu, 0xFFFFFFFFu, 0xFFFFFFFFu};
    #pragma unroll
    for (int mi = 0; mi < 2; mi++) {
        #pragma unroll
        for (int j = 0; j < 8; j++) {
            int nl = wn + j * 8 + ne;
            int bj0 = n0 + nl, bj1 = bj0 + 1;
            float sq0 = sSqJ[nl], sq1 = sSqJ[nl + 1];
            #pragma unroll
            for (int h = 0; h < 2; h++) {
                int bi = rowg[mi*2 + h];
                float d20 = fmaxf(sqi[mi*2+h] + sq0 - 2.f * acc[mi][j][h*2+0], 0.f);
                float d21 = fmaxf(sqi[mi*2+h] + sq1 - 2.f * acc[mi][j][h*2+1], 0.f);
                unsigned pk0 = (__float_as_uint(d20) & 0xFFFFF000u) | (unsigned)bj0;
                unsigned pk1 = (__float_as_uint(d21) & 0xFFFFF000u) | (unsigned)bj1;
                if (bj0 != bi) rmin[mi*2+h] = min(rmin[mi*2+h], pk0);
                if (bj1 != bi) rmin[mi*2+h] = min(rmin[mi*2+h], pk1);
                *(uint2*)&g_KEY[(size_t)bi * NB + bj0] = make_uint2(pk0, pk1);
            }
        }
    }
    const int cblk = blockIdx.x * 2 + (warp >> 2);
    #pragma unroll
    for (int r = 0; r < 4; r++) {
        unsigned m = rmin[r];
        m = min(m, __shfl_xor_sync(0xffffffffu, m, 1));
        m = min(m, __shfl_xor_sync(0xffffffffu, m, 2));
        if ((lane & 3) == 0) {
            g_BMIN[rowg[r] * 64 + cblk] = m;
            atomicMin(&g_row1[rowg[r]], m);
        }
    }
}

__global__ __launch_bounds__(256, 2) void gemm_kernel() {
    __shared__ __align__(16) uint4 sP[2][512];
    __shared__ __align__(16) uint4 sQ[2][512];
    __shared__ float sSqJ[128];
    if (blockIdx.z == 0) dbb_body(&sP[0][0], &sQ[0][0], sSqJ);
    else                 key_init_body(&sP[0][0], &sQ[0][0], sSqJ);
}

// ---------------- round 1: exact keyB repair + best assembly (-> buf 2) ----------------
__global__ __launch_bounds__(256) void round1_kernel(const float* __restrict__ batch,
                                                     const float* __restrict__ output) {
    int i = blockIdx.x * 256 + threadIdx.x;
    int a = (int)(g_amin[i] & 0xFFFu);

    const float4* pb = (const float4*)(output + (size_t)i * DIMK);
    const float4* pa = (const float4*)(batch  + (size_t)a * DIMK);
    float s = 0.f;
    #pragma unroll
    for (int q = 0; q < 32; q++) {
        float4 vb = pb[q], va = pa[q];
        float dx = vb.x - va.x, dy = vb.y - va.y, dz = vb.z - va.z, dw = vb.w - va.w;
        s += dx * dx + dy * dy + dz * dz + dw * dw;
    }
    unsigned d2b = __float_as_uint(s);
    g_key2min[i] = d2b;
    g_keyB[i]    = sqrtf(s);

    unsigned b32 = g_row1[i];
    unsigned j  = b32 & 0xFFFu;
    unsigned tw = b32 >> 12;
    unsigned lo = min((unsigned)i, j), hi = max((unsigned)i, j);
    ull kb = ((ull)tw << 26) | ((ull)lo << 13) | hi;

    unsigned tws = d2b >> 12;
    ull ksup = ((ull)tws << 26) | ((ull)(unsigned)i << 13) | SUPER;

    g_best3[2][i] = min(kb, ksup);

    ull w = ksup;
    #pragma unroll
    for (int o = 16; o; o >>= 1) w = min(w, __shfl_xor_sync(0xffffffffu, w, o));
    if ((threadIdx.x & 31) == 0) atomicMin(&g_best3[2][SUPER], w);
}

// ---------------- persistent Boruvka: MONOTONIC two-level tree barrier ----------------
__device__ __forceinline__ void grid_sync(unsigned& bar) {
    __syncthreads();
    if (threadIdx.x == 0) {
        __threadfence();
        int g = blockIdx.x & (NGRP - 1);
        unsigned t = atomicAdd(&g_grpcnt[g][0], 1u);
        if (t == bar * GRPSZ + (GRPSZ - 1u)) {
            unsigned m = atomicAdd(&g_mstcnt, 1u);
            if (m == bar * NGRP + (NGRP - 1u)) {
                __threadfence();
                g_barphase = bar + 1u;
            }
        }
        while (g_barphase <= bar) { }    // busy spin, no sleep
    }
    __syncthreads();
    bar++;
}

// scan: warp per row, a-priori-bound pruning (exact; see round-10 proof)
__device__ void scan_rows(const int* sC, ull* sSup, ull* bestW) {
    const int tid = threadIdx.x, warp = tid >> 5, lane = tid & 31;
    const int csup = sC[SUPER];

    ull mySup = ULLMAX;
    for (int i = blockIdx.x * 8 + warp; i < NB; i += NBLK * 8) {
        const int cu = sC[i];

        unsigned ksb   = g_key2min[i] >> 12;
        ull      bu    = __ldcg(&bestW[cu]);
        unsigned btw   = (unsigned)min(bu >> 26, (ull)0xFFFFFu);
        unsigned bound = min(btw, ksb);

        uint2 bm = *(const uint2*)&g_BMIN[i * 64 + lane * 2];
        unsigned m0 = __ballot_sync(0xffffffffu, (bm.x >> 12) <= bound);
        unsigned m1 = __ballot_sync(0xffffffffu, (bm.y >> 12) <= bound);
        ull mask = (ull)m0 | ((ull)m1 << 32);

        unsigned e = 0xFFFFFFFFu;
        const unsigned* rowp = g_KEY + (size_t)i * NB;
        while (mask) {
            int bit = __ffsll((long long)mask) - 1;
            mask &= mask - 1;
            int blk = (bit < 32) ? (bit * 2) : ((bit - 32) * 2 + 1);
            uint2 kv = *(const uint2*)&rowp[blk * 64 + lane * 2];
            if (sC[kv.x & 0xFFFu] != cu) e = min(e, kv.x);
            if (sC[kv.y & 0xFFFu] != cu) e = min(e, kv.y);
        }
        unsigned best = __reduce_min_sync(0xffffffffu, e);

        if (lane == 0) {
            ull kb = ULLMAX;
            if (best != 0xFFFFFFFFu) {
                unsigned j  = best & 0xFFFu;
                unsigned tw = best >> 12;
                unsigned lo = min((unsigned)i, j), hi = max((unsigned)i, j);
                kb = ((ull)tw << 26) | ((ull)lo << 13) | hi;
            }
            if (cu != csup) {
                ull ks = ((ull)ksb << 26) | ((ull)(unsigned)i << 13) | SUPER;
                kb = min(kb, ks);
                mySup = min(mySup, ks);
            }
            if (kb != ULLMAX) atomicMin(&bestW[cu], kb);
        }
    }
    if (lane == 0) sSup[warp] = mySup;
    __syncthreads();
    if (tid == 0) {
        ull m = ULLMAX;
        #pragma unroll
        for (int w = 0; w < 8; w++) m = min(m, sSup[w]);
        if (m != ULLMAX) atomicMin(&bestW[csup], m);
    }
    __syncthreads();
}

// merge: executed redundantly by ALL blocks (deterministic), block 0 records edges.
// Single global pass: (k, t) snapshots held in registers across one __syncthreads.
__device__ int merge_local(const ull* bestR, unsigned* selRow,
                           int* sC, int* sCnt) {
    const int tid = threadIdx.x, warp = tid >> 5, lane = tid & 31;

    ull kreg[17];
    int treg[17];
    #pragma unroll
    for (int q = 0; q < 17; q++) {
        int x = tid + q * 256;
        int t = -1; ull k = ULLMAX;
        if (x < NN && sC[x] == x) {
            k = __ldcg(&bestR[x]);
            if (k != ULLMAX) {
                int u  = (int)((k >> 13) & 0x1FFFu);
                int v  = (int)(k & 0x1FFFu);
                int c1 = sC[u], c2 = sC[v];
                t = (c1 == x) ? c2 : c1;
            }
        }
        kreg[q] = k; treg[q] = t;
    }
    __syncthreads();   // all sC reads done before any sC writes

    #pragma unroll
    for (int q = 0; q < 17; q++) {
        int x = tid + q * 256;
        int t = treg[q];
        if (t >= 0) {
            ull k = kreg[q];
            bool mutual = (__ldcg(&bestR[t]) == k);
            if (blockIdx.x == 0 && (!mutual || x < t)) {
                unsigned u = (unsigned)((k >> 13) & 0x1FFFu);
                unsigned v = (unsigned)(k & 0x1FFFu);
                selRow[x] = (u << 13) | v;
            }
            if (!(mutual && x < t)) sC[x] = t;
        }
    }
    __syncthreads();

    // pointer jumping with deterministic early exit (identical data in all blocks)
    for (int it = 0; it < 13; it++) {
        int v[17];
        int ch = 0;
        #pragma unroll
        for (int q = 0; q < 17; q++) {
            int x = tid + q * 256;
            if (x < NN) {
                int c = sC[x];
                v[q] = sC[c];
                ch |= (v[q] != c);
            } else v[q] = 0;
        }
        int any = __syncthreads_or(ch);
        if (!any) break;
        #pragma unroll
        for (int q = 0; q < 17; q++) {
            int x = tid + q * 256;
            if (x < NN) sC[x] = v[q];
        }
        __syncthreads();
    }

    int lcnt = 0;
    for (int x = tid; x < NN; x += 256) lcnt += (sC[x] == x);
    #pragma unroll
    for (int o = 16; o; o >>= 1) lcnt += __shfl_xor_sync(0xffffffffu, lcnt, o);
    if (lane == 0) sCnt[warp] = lcnt;
    __syncthreads();
    int nc = sCnt[0] + sCnt[1] + sCnt[2] + sCnt[3] +
             sCnt[4] + sCnt[5] + sCnt[6] + sCnt[7];
    __syncthreads();
    return nc;
}

__global__ __launch_bounds__(256, 2) void boruvka_kernel(const float* __restrict__ P,
                                                         float* __restrict__ out) {
    __shared__ __align__(16) int  sC[NN + 3];
    __shared__ ull   sSup[8];
    __shared__ int   sCnt[8];
    __shared__ float sRed[8];

    const int tid = threadIdx.x, warp = tid >> 5, lane = tid & 31;
    unsigned bar = 0u;
    for (int x = tid; x < NN; x += 256) sC[x] = x;
    __syncthreads();

    // rounds: merge r reads buf[(r+2)%3]; scan r writes buf[r%3], resets buf[(r+1)%3]
    for (int r = 0; r < 13; r++) {
        int nc = merge_local(g_best3[(r + 2) % 3], g_sel + r * NN, sC, sCnt);
        if (nc <= 1) break;

        ull* bestW = g_best3[r % 3];
        ull* bestZ = g_best3[(r + 1) % 3];
        for (int x = blockIdx.x * 256 + tid; x < NN; x += NBLK * 256) bestZ[x] = ULLMAX;
        scan_rows(sC, sSup, bestW);
        grid_sync(bar);
    }

    // finalize: make block0's g_sel visible, compute weights grid-wide, fixed-order sum
    grid_sync(bar);
    for (int slot = blockIdx.x * 256 + tid; slot < NSEL; slot += NBLK * 256) {
        unsigned s = __ldcg(&g_sel[slot]);
        if (s != 0xFFFFFFFFu) {
            int u = (int)(s >> 13), v = (int)(s & 0x1FFFu);
            float w;
            if (v == SUPER) {
                w = g_keyB[u];
            } else {
                const float4* pu = (const float4*)(P + (size_t)u * DIMK);
                const float4* pv = (const float4*)(P + (size_t)v * DIMK);
                float sum = 0.f;
                #pragma unroll 8
                for (int q = 0; q < 32; q++) {
                    float4 a = pu[q], b = pv[q];
                    float dx = a.x - b.x, dy = a.y - b.y, dz = a.z - b.z, dw = a.w - b.w;
                    sum += dx * dx + dy * dy + dz * dz + dw * dw;
                }
                w = sqrtf(sum);
            }
            g_ew[slot] = w;
        }
    }
    grid_sync(bar);

    if (blockIdx.x == 0) {
        // branchless fixed-order sum: g_ew is 0 for unused slots
        float ls = 0.f;
        const float4* ew4 = (const float4*)g_ew;       // NSEL+3 = 53264 = 13316 float4
        for (int q = tid; q < (NSEL + 3) / 4; q += 256) {
            float4 v = __ldcg(&ew4[q]);
            ls += (v.x + v.y) + (v.z + v.w);
        }
        #pragma unroll
        for (int o = 16; o; o >>= 1) ls += __shfl_xor_sync(0xffffffffu, ls, o);
        if (lane == 0) sRed[warp] = ls;
        __syncthreads();
        if (tid == 0) {
            float tot = 0.f;
            #pragma unroll
            for (int w = 0; w < 8; w++) tot += sRed[w];
            out[0] = tot;
        }
    }
}

// ---------------- launch ----------------
extern "C" void kernel_launch(void* const* d_in, const int* in_sizes, int n_in,
                              void* d_out, int out_size)
{
    const float* batch  = (const float*)d_in[0];   // [16384,128]
    const float* output = (const float*)d_in[1];   // [4096,128]
    float* out = (float*)d_out;

    prep_kernel<<<(NA + NB) / 8, 256>>>(batch, output);

    dim3 gg(NB / 128, NB / 128, 2);
    gemm_kernel<<<gg, 256>>>();

    round1_kernel<<<NB / 256, 256>>>(batch, output);

    boruvka_kernel<<<NBLK, 256>>>(output, out);
}

// round 16
// speedup vs baseline: 2.2954x; 1.1299x over previous
#include <cuda_runtime.h>
#include <cuda_bf16.h>
#include <math_constants.h>

#define NA    4096
#define NB    4096
#define DIMK  128
#define NN    4097
#define SUPER 4096
#define ULLMAX 0xFFFFFFFFFFFFFFFFULL
#define NBLK  148          // persistent grid: 1 block/SM; 148 = 4 * 37
#define NGRP  4
#define GRPSZ 37
#define NSEL  (13 * NN)

typedef unsigned long long ull;
typedef unsigned short u16;

// ---------------- scratch ----------------
__device__ __align__(16) float    g_sqA[NA];
__device__ __align__(16) float    g_sqB[NB];
__device__ __align__(16) float    g_keyB[NB];      // exact sqrt(d^2(b, a*))
__device__ __align__(16) unsigned g_key2min[NB];   // exact fp32 bits of d^2(b, a*)
__device__ __align__(16) unsigned g_amin[NB];      // packed (approx d2 | a idx)
__device__ __align__(16) unsigned g_row1[NB];      // round-1 per-row min packed key
__device__ __align__(16) unsigned g_Abf[NA * 64];  // bf16x2 packed A points
__device__ __align__(16) unsigned g_Bbf[NB * 64];  // bf16x2 packed B points
__device__ __align__(16) unsigned g_BMIN[NB * 64]; // per-row per-64col block min (1MB)
__device__ __align__(16) unsigned g_KEY[(size_t)NB * NB];  // 64MB packed (d2w20|col12)
__device__ __align__(16) ull      g_best3[3][NN];  // rotating best buffers
__device__ __align__(16) unsigned g_sel[NSEL];     // per (round,root) selected edge (u13|v13)
__device__ __align__(16) float    g_ew[NSEL + 3];  // per-slot exact weight (0 if unused)
__device__ __align__(128) unsigned g_grpcnt[NGRP][32];  // padded, MONOTONIC group counters
__device__ unsigned          g_mstcnt;                  // monotonic master counter
__device__ volatile unsigned g_barphase;                // monotonic phase

// ---------------- prep: norms + bf16x2 pack + all state init ----------------
__global__ __launch_bounds__(256) void prep_kernel(const float* __restrict__ batch,
                                                   const float* __restrict__ output) {
    int row  = blockIdx.x * 8 + (threadIdx.x >> 5);
    int lane = threadIdx.x & 31;
    bool isA = row < NA;
    const float* src = isA ? (batch + (size_t)row * DIMK)
                           : (output + (size_t)(row - NA) * DIMK);
    float4 v = ((const float4*)src)[lane];
    float s = v.x * v.x + v.y * v.y + v.z * v.z + v.w * v.w;

    __nv_bfloat162 b0 = __float22bfloat162_rn(make_float2(v.x, v.y));
    __nv_bfloat162 b1 = __float22bfloat162_rn(make_float2(v.z, v.w));
    uint2 w;
    w.x = *reinterpret_cast<unsigned*>(&b0);
    w.y = *reinterpret_cast<unsigned*>(&b1);
    unsigned* dst = isA ? (g_Abf + (size_t)row * 64) : (g_Bbf + (size_t)(row - NA) * 64);
    *(uint2*)(dst + lane * 2) = w;

    #pragma unroll
    for (int o = 16; o; o >>= 1) s += __shfl_down_sync(0xffffffffu, s, o);
    if (lane == 0) {
        if (isA) g_sqA[row] = s;
        else     g_sqB[row - NA] = s;
    }

    // fused state init (grid = 1024x256 = 262144 threads)
    int gid = blockIdx.x * 256 + threadIdx.x;
    if (gid < NN) {
        g_best3[0][gid] = ULLMAX;
        g_best3[1][gid] = ULLMAX;
        g_best3[2][gid] = ULLMAX;
    }
    if (gid < NB) { g_row1[gid] = 0xFFFFFFFFu; g_amin[gid] = 0xFFFFFFFFu; }
    if (gid < NGRP)  g_grpcnt[gid][0] = 0u;
    if (gid == NGRP) { g_mstcnt = 0u; g_barphase = 0u; }
    for (int t = gid; t < NSEL; t += 262144) { g_sel[t] = 0xFFFFFFFFu; g_ew[t] = 0.f; }
    if (gid < 3) g_ew[NSEL + gid] = 0.f;
}

// ---------------- MMA + cp.async helpers ----------------
__device__ __forceinline__ void ldmx4(unsigned addr, unsigned& r0, unsigned& r1,
                                      unsigned& r2, unsigned& r3) {
    asm volatile("ldmatrix.sync.aligned.m8n8.x4.shared.b16 {%0,%1,%2,%3}, [%4];"
                 : "=r"(r0), "=r"(r1), "=r"(r2), "=r"(r3) : "r"(addr));
}
__device__ __forceinline__ void ldmx2(unsigned addr, unsigned& r0, unsigned& r1) {
    asm volatile("ldmatrix.sync.aligned.m8n8.x2.shared.b16 {%0,%1}, [%2];"
                 : "=r"(r0), "=r"(r1) : "r"(addr));
}
__device__ __forceinline__ void mma_bf16(float* c, unsigned a0, unsigned a1,
                                         unsigned a2, unsigned a3,
                                         unsigned b0, unsigned b1) {
    asm volatile("mma.sync.aligned.m16n8k16.row.col.f32.bf16.bf16.f32 "
                 "{%0,%1,%2,%3},{%4,%5,%6,%7},{%8,%9},{%0,%1,%2,%3};"
                 : "+f"(c[0]), "+f"(c[1]), "+f"(c[2]), "+f"(c[3])
                 : "r"(a0), "r"(a1), "r"(a2), "r"(a3), "r"(b0), "r"(b1));
}
__device__ __forceinline__ void cpa16(unsigned dst, const void* src) {
    asm volatile("cp.async.cg.shared.global [%0], [%1], 16;" :: "r"(dst), "l"(src));
}
__device__ __forceinline__ void cpa_commit() { asm volatile("cp.async.commit_group;"); }
template<int N> __device__ __forceinline__ void cpa_wait() {
    asm volatile("cp.async.wait_group %0;" :: "n"(N));
}

__device__ __forceinline__ void load_chunk_async(unsigned sbase,
                                                 const unsigned* __restrict__ gsrc, int kc) {
    int tid = threadIdx.x;
    #pragma unroll
    for (int it = 0; it < 2; it++) {
        int f = tid + it * 256;
        int r = f >> 2, g = f & 3;
        cpa16(sbase + (unsigned)((r * 4 + (g ^ (r & 3))) << 4),
              gsrc + (size_t)r * 64 + kc * 16 + g * 4);
    }
}
__device__ __forceinline__ unsigned chunk_addr(unsigned base, int row, int g) {
    return base + (unsigned)((row * 4 + (g ^ (row & 3))) << 4);
}
__device__ __forceinline__ void afrag(unsigned base, int mt, int s, int lane,
                                      unsigned& a0, unsigned& a1, unsigned& a2, unsigned& a3) {
    int row = mt + (lane & 7) + ((lane >> 3) & 1) * 8;
    int g   = s * 2 + (lane >> 4);
    ldmx4(chunk_addr(base, row, g), a0, a1, a2, a3);
}
__device__ __forceinline__ void bfrag(unsigned base, int nt, int s, int lane,
                                      unsigned& b0, unsigned& b1) {
    int l15 = lane & 15;
    int row = nt + (l15 & 7);
    int g   = s * 2 + ((l15 >> 3) & 1);
    ldmx2(chunk_addr(base, row, g), b0, b1);
}

__device__ __forceinline__ void mma_mainloop(unsigned basePu, unsigned baseQu,
                                             const unsigned* gP, const unsigned* gQ,
                                             float acc[2][8][4], int wm, int wn, int lane) {
    load_chunk_async(basePu, gP, 0);
    load_chunk_async(baseQu, gQ, 0);
    cpa_commit();
    #pragma unroll
    for (int kc = 0; kc < 4; kc++) {
        if (kc < 3) {
            unsigned off = (kc & 1) ? 0u : 8192u;
            load_chunk_async(basePu + off, gP, kc + 1);
            load_chunk_async(baseQu + off, gQ, kc + 1);
            cpa_commit();
            cpa_wait<1>();
        } else {
            cpa_wait<0>();
        }
        __syncthreads();
        unsigned off = (kc & 1) ? 8192u : 0u;
        #pragma unroll
        for (int s = 0; s < 2; s++) {
            unsigned a00, a01, a02, a03, a10, a11, a12, a13;
            afrag(basePu + off, wm,      s, lane, a00, a01, a02, a03);
            afrag(basePu + off, wm + 16, s, lane, a10, a11, a12, a13);
            #pragma unroll
            for (int j = 0; j < 8; j++) {
                unsigned b0, b1;
                bfrag(baseQu + off, wn + j * 8, s, lane, b0, b1);
                mma_bf16(acc[0][j], a00, a01, a02, a03, b0, b1);
                mma_bf16(acc[1][j], a10, a11, a12, a13, b0, b1);
            }
        }
        __syncthreads();
    }
}

// ---------------- fused GEMM kernel: z=0 -> dbb, z=1 -> key_init ----------------
__device__ void key_init_body(uint4* sP, uint4* sQ, float* sSqJ) {
    const int tid = threadIdx.x, warp = tid >> 5, lane = tid & 31;
    const int m0 = blockIdx.y * 128;
    const int n0 = blockIdx.x * 128;
    const int wm = (warp & 3) * 32;
    const int wn = (warp >> 2) * 64;

    if (tid < 128) sSqJ[tid] = g_sqA[n0 + tid];

    unsigned basePu = (unsigned)__cvta_generic_to_shared(sP);
    unsigned baseQu = (unsigned)__cvta_generic_to_shared(sQ);

    float acc[2][8][4];
    #pragma unroll
    for (int mi = 0; mi < 2; mi++)
        #pragma unroll
        for (int j = 0; j < 8; j++)
            #pragma unroll
            for (int e = 0; e < 4; e++) acc[mi][j][e] = 0.f;

    mma_mainloop(basePu, baseQu, g_Bbf + (size_t)m0 * 64, g_Abf + (size_t)n0 * 64,
                 acc, wm, wn, lane);

    const int mlo = lane >> 2, ne = (lane & 3) * 2;
    float sqi[4];
    #pragma unroll
    for (int mi = 0; mi < 2; mi++) {
        sqi[mi * 2 + 0] = g_sqB[m0 + wm + mi * 16 + mlo];
        sqi[mi * 2 + 1] = g_sqB[m0 + wm + mi * 16 + 8 + mlo];
    }
    unsigned rmin[4] = {0xFFFFFFFFu, 0xFFFFFFFFu, 0xFFFFFFFFu, 0xFFFFFFFFu};
    #pragma unroll
    for (int mi = 0; mi < 2; mi++) {
        #pragma unroll
        for (int j = 0; j < 8; j++) {
            int nl = wn + j * 8 + ne;
            float sq0 = sSqJ[nl], sq1 = sSqJ[nl + 1];
            unsigned aj0 = (unsigned)(n0 + nl), aj1 = aj0 + 1;
            float d2;
            d2 = fmaxf(sqi[mi*2] + sq0 - 2.f * acc[mi][j][0], 0.f);
            rmin[mi*2]   = min(rmin[mi*2],   (__float_as_uint(d2) & 0xFFFFF000u) | aj0);
            d2 = fmaxf(sqi[mi*2] + sq1 - 2.f * acc[mi][j][1], 0.f);
            rmin[mi*2]   = min(rmin[mi*2],   (__float_as_uint(d2) & 0xFFFFF000u) | aj1);
            d2 = fmaxf(sqi[mi*2+1] + sq0 - 2.f * acc[mi][j][2], 0.f);
            rmin[mi*2+1] = min(rmin[mi*2+1], (__float_as_uint(d2) & 0xFFFFF000u) | aj0);
            d2 = fmaxf(sqi[mi*2+1] + sq1 - 2.f * acc[mi][j][3], 0.f);
            rmin[mi*2+1] = min(rmin[mi*2+1], (__float_as_uint(d2) & 0xFFFFF000u) | aj1);
        }
    }
    #pragma unroll
    for (int r = 0; r < 4; r++) {
        unsigned m = rmin[r];
        m = min(m, __shfl_xor_sync(0xffffffffu, m, 1));
        m = min(m, __shfl_xor_sync(0xffffffffu, m, 2));
        if ((lane & 3) == 0) {
            int row = m0 + wm + (r >> 1) * 16 + ((r & 1) ? 8 : 0) + mlo;
            atomicMin(&g_amin[row], m);
        }
    }
}

__device__ void dbb_body(uint4* sP, uint4* sQ, float* sSqJ) {
    const int tid = threadIdx.x, warp = tid >> 5, lane = tid & 31;
    const int m0 = blockIdx.y * 128;
    const int n0 = blockIdx.x * 128;
    const int wm = (warp & 3) * 32;
    const int wn = (warp >> 2) * 64;

    if (tid < 128) sSqJ[tid] = g_sqB[n0 + tid];

    unsigned basePu = (unsigned)__cvta_generic_to_shared(sP);
    unsigned baseQu = (unsigned)__cvta_generic_to_shared(sQ);

    float acc[2][8][4];
    #pragma unroll
    for (int mi = 0; mi < 2; mi++)
        #pragma unroll
        for (int j = 0; j < 8; j++)
            #pragma unroll
            for (int e = 0; e < 4; e++) acc[mi][j][e] = 0.f;

    mma_mainloop(basePu, baseQu, g_Bbf + (size_t)m0 * 64, g_Bbf + (size_t)n0 * 64,
                 acc, wm, wn, lane);

    const int mlo = lane >> 2, ne = (lane & 3) * 2;
    float sqi[4];
    int rowg[4];
    #pragma unroll
    for (int mi = 0; mi < 2; mi++) {
        rowg[mi*2]   = m0 + wm + mi * 16 + mlo;
        rowg[mi*2+1] = m0 + wm + mi * 16 + 8 + mlo;
        sqi[mi*2]    = g_sqB[rowg[mi*2]];
        sqi[mi*2+1]  = g_sqB[rowg[mi*2+1]];
    }
    unsigned rmin[4] = {0xFFFFFFFFu, 0xFFFFFFFFu, 0xFFFFFFFFu, 0xFFFFFFFFu};
    #pragma unroll
    for (int mi = 0; mi < 2; mi++) {
        #pragma unroll
        for (int j = 0; j < 8; j++) {
            int nl = wn + j * 8 + ne;
            int bj0 = n0 + nl, bj1 = bj0 + 1;
            float sq0 = sSqJ[nl], sq1 = sSqJ[nl + 1];
            #pragma unroll
            for (int h = 0; h < 2; h++) {
                int bi = rowg[mi*2 + h];
                float d20 = fmaxf(sqi[mi*2+h] + sq0 - 2.f * acc[mi][j][h*2+0], 0.f);
                float d21 = fmaxf(sqi[mi*2+h] + sq1 - 2.f * acc[mi][j][h*2+1], 0.f);
                unsigned pk0 = (__float_as_uint(d20) & 0xFFFFF000u) | (unsigned)bj0;
                unsigned pk1 = (__float_as_uint(d21) & 0xFFFFF000u) | (unsigned)bj1;
                if (bj0 != bi) rmin[mi*2+h] = min(rmin[mi*2+h], pk0);
                if (bj1 != bi) rmin[mi*2+h] = min(rmin[mi*2+h], pk1);
                *(uint2*)&g_KEY[(size_t)bi * NB + bj0] = make_uint2(pk0, pk1);
            }
        }
    }
    const int cblk = blockIdx.x * 2 + (warp >> 2);
    #pragma unroll
    for (int r = 0; r < 4; r++) {
        unsigned m = rmin[r];
        m = min(m, __shfl_xor_sync(0xffffffffu, m, 1));
        m = min(m, __shfl_xor_sync(0xffffffffu, m, 2));
        if ((lane & 3) == 0) {
            g_BMIN[rowg[r] * 64 + cblk] = m;
            atomicMin(&g_row1[rowg[r]], m);
        }
    }
}

__global__ __launch_bounds__(256, 2) void gemm_kernel() {
    __shared__ __align__(16) uint4 sP[2][512];
    __shared__ __align__(16) uint4 sQ[2][512];
    __shared__ float sSqJ[128];
    if (blockIdx.z == 0) dbb_body(&sP[0][0], &sQ[0][0], sSqJ);
    else                 key_init_body(&sP[0][0], &sQ[0][0], sSqJ);
}

// ---------------- round 1: exact keyB repair + best assembly (-> buf 2) ----------------
__global__ __launch_bounds__(256) void round1_kernel(const float* __restrict__ batch,
                                                     const float* __restrict__ output) {
    int i = blockIdx.x * 256 + threadIdx.x;
    int a = (int)(g_amin[i] & 0xFFFu);

    const float4* pb = (const float4*)(output + (size_t)i * DIMK);
    const float4* pa = (const float4*)(batch  + (size_t)a * DIMK);
    float s = 0.f;
    #pragma unroll
    for (int q = 0; q < 32; q++) {
        float4 vb = pb[q], va = pa[q];
        float dx = vb.x - va.x, dy = vb.y - va.y, dz = vb.z - va.z, dw = vb.w - va.w;
        s += dx * dx + dy * dy + dz * dz + dw * dw;
    }
    unsigned d2b = __float_as_uint(s);
    g_key2min[i] = d2b;
    g_keyB[i]    = sqrtf(s);

    unsigned b32 = g_row1[i];
    unsigned j  = b32 & 0xFFFu;
    unsigned tw = b32 >> 12;
    unsigned lo = min((unsigned)i, j), hi = max((unsigned)i, j);
    ull kb = ((ull)tw << 26) | ((ull)lo << 13) | hi;

    unsigned tws = d2b >> 12;
    ull ksup = ((ull)tws << 26) | ((ull)(unsigned)i << 13) | SUPER;

    g_best3[2][i] = min(kb, ksup);

    ull w = ksup;
    #pragma unroll
    for (int o = 16; o; o >>= 1) w = min(w, __shfl_xor_sync(0xffffffffu, w, o));
    if ((threadIdx.x & 31) == 0) atomicMin(&g_best3[2][SUPER], w);
}

// ---------------- persistent Boruvka: MONOTONIC two-level tree barrier ----------------
__device__ __forceinline__ void grid_sync(unsigned& bar) {
    __syncthreads();
    if (threadIdx.x == 0) {
        __threadfence();
        int g = blockIdx.x & (NGRP - 1);
        unsigned t = atomicAdd(&g_grpcnt[g][0], 1u);
        if (t == bar * GRPSZ + (GRPSZ - 1u)) {
            unsigned m = atomicAdd(&g_mstcnt, 1u);
            if (m == bar * NGRP + (NGRP - 1u)) {
                __threadfence();
                g_barphase = bar + 1u;
            }
        }
        while (g_barphase <= bar) { }    // busy spin
    }
    __syncthreads();
    bar++;
}

// scan: warp per row, a-priori-bound pruning (exact; see round-10 proof).
// All keys destined for bestW[csup] folded into per-block min -> ONE atomic per block.
__device__ void scan_rows(const u16* sC, ull* sSup, ull* bestW) {
    const int tid = threadIdx.x, warp = tid >> 5, lane = tid & 31;
    const int csup = (int)sC[SUPER];

    ull mySup = ULLMAX;
    for (int i = blockIdx.x * 8 + warp; i < NB; i += NBLK * 8) {
        const int cu = (int)sC[i];

        unsigned ksb   = g_key2min[i] >> 12;
        ull      bu    = __ldcg(&bestW[cu]);
        unsigned btw   = (unsigned)min(bu >> 26, (ull)0xFFFFFu);
        unsigned bound = min(btw, ksb);

        uint2 bm = *(const uint2*)&g_BMIN[i * 64 + lane * 2];
        unsigned m0 = __ballot_sync(0xffffffffu, (bm.x >> 12) <= bound);
        unsigned m1 = __ballot_sync(0xffffffffu, (bm.y >> 12) <= bound);
        ull mask = (ull)m0 | ((ull)m1 << 32);

        unsigned e = 0xFFFFFFFFu;
        const unsigned* rowp = g_KEY + (size_t)i * NB;
        while (mask) {
            int bit = __ffsll((long long)mask) - 1;
            mask &= mask - 1;
            int blk = (bit < 32) ? (bit * 2) : ((bit - 32) * 2 + 1);
            uint2 kv = *(const uint2*)&rowp[blk * 64 + lane * 2];
            if ((int)sC[kv.x & 0xFFFu] != cu) e = min(e, kv.x);
            if ((int)sC[kv.y & 0xFFFu] != cu) e = min(e, kv.y);
        }
        unsigned best = __reduce_min_sync(0xffffffffu, e);

        if (lane == 0) {
            ull kb = ULLMAX;
            if (best != 0xFFFFFFFFu) {
                unsigned j  = best & 0xFFFu;
                unsigned tw = best >> 12;
                unsigned lo = min((unsigned)i, j), hi = max((unsigned)i, j);
                kb = ((ull)tw << 26) | ((ull)lo << 13) | hi;
            }
            if (cu != csup) {
                ull ks = ((ull)ksb << 26) | ((ull)(unsigned)i << 13) | SUPER;
                mySup = min(mySup, ks);
                kb = min(kb, ks);
                if (kb != ULLMAX) atomicMin(&bestW[cu], kb);
            } else {
                mySup = min(mySup, kb);
            }
        }
    }
    if (lane == 0) sSup[warp] = mySup;
    __syncthreads();
    if (tid == 0) {
        ull m = ULLMAX;
        #pragma unroll
        for (int w = 0; w < 8; w++) m = min(m, sSup[w]);
        if (m != ULLMAX) atomicMin(&bestW[csup], m);
    }
    __syncthreads();
}

// merge: executed redundantly by ALL blocks (deterministic), block 0 records edges.
// bestR staged into smem first (coalesced stream); all lookups LDS-speed.
__device__ int merge_local(const ull* bestR, unsigned* selRow,
                           u16* sC, ull* sB, int* sCnt) {
    const int tid = threadIdx.x, warp = tid >> 5, lane = tid & 31;

    for (int x = tid; x < NN; x += 256) sB[x] = __ldcg(&bestR[x]);
    __syncthreads();

    ull kreg[17];
    int treg[17];
    #pragma unroll
    for (int q = 0; q < 17; q++) {
        int x = tid + q * 256;
        int t = -1; ull k = ULLMAX;
        if (x < NN && (int)sC[x] == x) {
            k = sB[x];
            if (k != ULLMAX) {
                int u  = (int)((k >> 13) & 0x1FFFu);
                int v  = (int)(k & 0x1FFFu);
                int c1 = (int)sC[u], c2 = (int)sC[v];
                t = (c1 == x) ? c2 : c1;
            }
        }
        kreg[q] = k; treg[q] = t;
    }
    __syncthreads();   // all sC reads done before any sC writes

    #pragma unroll
    for (int q = 0; q < 17; q++) {
        int x = tid + q * 256;
        int t = treg[q];
        if (t >= 0) {
            ull k = kreg[q];
            bool mutual = (sB[t] == k);
            if (blockIdx.x == 0 && (!mutual || x < t)) {
                unsigned u = (unsigned)((k >> 13) & 0x1FFFu);
                unsigned v = (unsigned)(k & 0x1FFFu);
                selRow[x] = (u << 13) | v;
            }
            if (!(mutual && x < t)) sC[x] = (u16)t;
        }
    }
    __syncthreads();

    // pointer jumping with deterministic early exit (identical data in all blocks)
    for (int it = 0; it < 13; it++) {
        int v[17];
        int ch = 0;
        #pragma unroll
        for (int q = 0; q < 17; q++) {
            int x = tid + q * 256;
            if (x < NN) {
                int c = (int)sC[x];
                v[q] = (int)sC[c];
                ch |= (v[q] != c);
            } else v[q] = 0;
        }
        int any = __syncthreads_or(ch);
        if (!any) break;
        #pragma unroll
        for (int q = 0; q < 17; q++) {
            int x = tid + q * 256;
            if (x < NN) sC[x] = (u16)v[q];
        }
        __syncthreads();
    }

    int lcnt = 0;
    for (int x = tid; x < NN; x += 256) lcnt += ((int)sC[x] == x);
    #pragma unroll
    for (int o = 16; o; o >>= 1) lcnt += __shfl_xor_sync(0xffffffffu, lcnt, o);
    if (lane == 0) sCnt[warp] = lcnt;
    __syncthreads();
    int nc = sCnt[0] + sCnt[1] + sCnt[2] + sCnt[3] +
             sCnt[4] + sCnt[5] + sCnt[6] + sCnt[7];
    __syncthreads();
    return nc;
}

__global__ __launch_bounds__(256, 1) void boruvka_kernel(const float* __restrict__ P,
                                                         float* __restrict__ out) {
    __shared__ __align__(16) u16 sC[NN + 7];   // 8.2 KB (comp ids fit in 13 bits)
    __shared__ __align__(16) ull sB[NN];       // 32.8 KB
    __shared__ ull   sSup[8];
    __shared__ int   sCnt[8];
    __shared__ float sRed[8];

    const int tid = threadIdx.x, warp = tid >> 5, lane = tid & 31;
    unsigned bar = 0u;
    for (int x = tid; x < NN; x += 256) sC[x] = (u16)x;
    __syncthreads();

    // rounds: merge r reads buf[(r+2)%3]; scan r writes buf[r%3], resets buf[(r+1)%3]
    for (int r = 0; r < 13; r++) {
        int nc = merge_local(g_best3[(r + 2) % 3], g_sel + r * NN, sC, sB, sCnt);
        if (nc <= 1) break;

        ull* bestW = g_best3[r % 3];
        ull* bestZ = g_best3[(r + 1) % 3];
        for (int x = blockIdx.x * 256 + tid; x < NN; x += NBLK * 256) bestZ[x] = ULLMAX;
        scan_rows(sC, sSup, bestW);
        grid_sync(bar);
    }

    // finalize: make block0's g_sel visible, compute weights grid-wide, fixed-order sum
    grid_sync(bar);
    for (int slot = blockIdx.x * 256 + tid; slot < NSEL; slot += NBLK * 256) {
        unsigned s = __ldcg(&g_sel[slot]);
        if (s != 0xFFFFFFFFu) {
            int u = (int)(s >> 13), v = (int)(s & 0x1FFFu);
            float w;
            if (v == SUPER) {
                w = g_keyB[u];
            } else {
                const float4* pu = (const float4*)(P + (size_t)u * DIMK);
                const float4* pv = (const float4*)(P + (size_t)v * DIMK);
                float sum = 0.f;
                #pragma unroll 8
                for (int q = 0; q < 32; q++) {
                    float4 a = pu[q], b = pv[q];
                    float dx = a.x - b.x, dy = a.y - b.y, dz = a.z - b.z, dw = a.w - b.w;
                    sum += dx * dx + dy * dy + dz * dz + dw * dw;
                }
                w = sqrtf(sum);
            }
            g_ew[slot] = w;
        }
    }
    grid_sync(bar);

    if (blockIdx.x == 0) {
        // branchless fixed-order sum: g_ew is 0 for unused slots
        float ls = 0.f;
        const float4* ew4 = (const float4*)g_ew;       // NSEL+3 = 53264 = 13316 float4
        for (int q = tid; q < (NSEL + 3) / 4; q += 256) {
            float4 v = __ldcg(&ew4[q]);
            ls += (v.x + v.y) + (v.z + v.w);
        }
        #pragma unroll
        for (int o = 16; o; o >>= 1) ls += __shfl_xor_sync(0xffffffffu, ls, o);
        if (lane == 0) sRed[warp] = ls;
        __syncthreads();
        if (tid == 0) {
            float tot = 0.f;
            #pragma unroll
            for (int w = 0; w < 8; w++) tot += sRed[w];
            out[0] = tot;
        }
    }
}

// ---------------- launch ----------------
extern "C" void kernel_launch(void* const* d_in, const int* in_sizes, int n_in,
                              void* d_out, int out_size)
{
    const float* batch  = (const float*)d_in[0];   // [16384,128]
    const float* output = (const float*)d_in[1];   // [4096,128]
    float* out = (float*)d_out;

    prep_kernel<<<(NA + NB) / 8, 256>>>(batch, output);

    dim3 gg(NB / 128, NB / 128, 2);
    gemm_kernel<<<gg, 256>>>();

    round1_kernel<<<NB / 256, 256>>>(batch, output);

    boruvka_kernel<<<NBLK, 256>>>(output, out);
}